// round 13
// baseline (speedup 1.0000x reference)
#include <cuda_runtime.h>
#include <cuda_fp16.h>
#include <cstdint>
#include <cstring>

// Problem constants (fixed by the dataset)
#define B_    16
#define MC    2048
#define MT    4096
#define E_    512
#define VOCAB 32000
#define NREL  69

#define NROW_H (B_ * MC)   // 32768
#define NROW_R (B_ * MT)   // 65536
#define MAT    (E_ * E_)   // 262144

// ---------------- scratch (static device globals; no allocation allowed) ---
__device__ __half g_ct16[VOCAB * E_];            // fp16 concept table
__device__ __half g_rt16[NREL * E_];             // fp16 relation table
__device__ __half g_wr16[2 * MAT];               // fp16 plain Wr0, Wr1
__device__ __half g_R0h [NREL * E_];             // r embeddings after hop 0
__device__ float  g_R1f [NREL * E_];             // r embeddings after hop 1
__device__ __half g_h16[NROW_H * E_];            // h after hop 0 (fp16)
__device__ __half g_h2h[NROW_H * E_];            // h after hop 1 (fp16)
__device__ float  g_upd0[NROW_H * E_ + NROW_H];  // hop-0 upd (+cnt tail)
__device__ float  g_upd1[NROW_H * E_ + NROW_H];  // hop-1 upd (+cnt tail)
__device__ __half g_wf [4 * MAT];                // fp16 pre-swizzled weights
                                                 // [Ws0,Ws1,Wn0,Wn1]

// ---------------- bit-cast helper --------------------------------------------
__device__ __forceinline__ uint32_t h2u(__half2 v) {
    uint32_t r;
    memcpy(&r, &v, 4);
    return r;
}

// ---------------- mma / ldmatrix helpers -------------------------------------
__device__ __forceinline__ void ldsm4(uint32_t* r, uint32_t addr) {
    asm volatile("ldmatrix.sync.aligned.m8n8.x4.shared.b16 {%0,%1,%2,%3}, [%4];"
                 : "=r"(r[0]), "=r"(r[1]), "=r"(r[2]), "=r"(r[3]) : "r"(addr));
}

__device__ __forceinline__ void mma_fp16(float* c, const uint32_t* a,
                                         uint32_t b0, uint32_t b1) {
    asm volatile(
        "mma.sync.aligned.m16n8k16.row.col.f32.f16.f16.f32 "
        "{%0,%1,%2,%3}, {%4,%5,%6,%7}, {%8,%9}, {%0,%1,%2,%3};\n"
        : "+f"(c[0]), "+f"(c[1]), "+f"(c[2]), "+f"(c[3])
        : "r"(a[0]), "r"(a[1]), "r"(a[2]), "r"(a[3]), "r"(b0), "r"(b1));
}

// ---------------- fp32 -> fp16 conversion ------------------------------------
__global__ void to_half(const float* __restrict__ src, __half* __restrict__ dst,
                        int n8) {
    const int i = blockIdx.x * 256 + threadIdx.x;   // one 8-elem chunk each
    if (i >= n8) return;
    float4 a = ((const float4*)src)[2 * i];
    float4 b = ((const float4*)src)[2 * i + 1];
    uint4 o;
    o.x = h2u(__floats2half2_rn(a.x, a.y));
    o.y = h2u(__floats2half2_rn(a.z, a.w));
    o.z = h2u(__floats2half2_rn(b.x, b.y));
    o.w = h2u(__floats2half2_rn(b.z, b.w));
    ((uint4*)dst)[i] = o;
}

// ---------------- weight prep: fp32 row-major -> fp16 pre-swizzled tiles ----
// Only Ws0,Ws1,Wn0,Wn1 (the big h-GEMMs). Layout as in prior rounds.
__global__ void prep_weights(const float* __restrict__ Ws,
                             const float* __restrict__ Wn,
                             __half* __restrict__ dst) {
    const int idx = blockIdx.x * 256 + threadIdx.x;   // one 16B unit each
    const int mat  = idx >> 15;                       // 0..3
    const int rem  = idx & 32767;
    const int p    = rem >> 14;
    const int s    = (rem >> 10) & 15;
    const int nl   = (rem >> 2) & 255;
    const int u    = rem & 3;
    const float* src = (mat < 2) ? Ws + (size_t)mat * MAT
                                 : Wn + (size_t)(mat - 2) * MAT;
    const float* sp = src + (size_t)(p * 256 + nl) * E_ + s * 32 + u * 8;
    float4 v0 = ((const float4*)sp)[0];
    float4 v1 = ((const float4*)sp)[1];
    uint4 o;
    o.x = h2u(__floats2half2_rn(v0.x, v0.y));
    o.y = h2u(__floats2half2_rn(v0.z, v0.w));
    o.z = h2u(__floats2half2_rn(v1.x, v1.y));
    o.w = h2u(__floats2half2_rn(v1.z, v1.w));
    const int up = u ^ ((nl >> 1) & 3);
    *(uint4*)(dst + (size_t)mat * MAT + ((p * 16 + s) * 8192) + nl * 32 + up * 8) = o;
}

// ---------------- tiny r-GEMM: out[row][n] = sum_k A[row][k] * W[n][k] -------
// rows = NREL (69). One block per row, 512 threads = one output column each.
template<bool OUT16>
__global__ void __launch_bounds__(512)
small_gemm(const __half* __restrict__ A, const __half* __restrict__ W,
           __half* __restrict__ out16, float* __restrict__ out32) {
    __shared__ float arow[E_];
    const int row = blockIdx.x;
    const int n   = threadIdx.x;
    if (n < 256) {
        float2 f = __half22float2(((const __half2*)(A + (size_t)row * E_))[n]);
        arow[2 * n]     = f.x;
        arow[2 * n + 1] = f.y;
    }
    __syncthreads();
    const __half2* w2 = (const __half2*)(W + (size_t)n * E_);
    float s = 0.0f;
    #pragma unroll 16
    for (int k = 0; k < E_ / 2; ++k) {
        float2 wf = __half22float2(w2[k]);
        s += arow[2 * k] * wf.x + arow[2 * k + 1] * wf.y;
    }
    if (OUT16) out16[(size_t)row * E_ + n] = __float2half_rn(s);
    else       out32[(size_t)row * E_ + n] = s;
}

// ---------------- scatter messages + degree counts (vector red) -------------
__device__ __forceinline__ void red4(float* p, float a, float b, float c, float d) {
    asm volatile("red.global.add.v4.f32 [%0], {%1, %2, %3, %4};"
                 :: "l"(p), "f"(a), "f"(b), "f"(c), "f"(d) : "memory");
}

__device__ __forceinline__ float4 ld_half4(const __half* p, int o) {
    const __half2* q = (const __half2*)(p + o);
    float2 f0 = __half22float2(q[0]);
    float2 f1 = __half22float2(q[1]);
    return make_float4(f0.x, f0.y, f1.x, f1.y);
}

// FIRST: h rows via concept_ids indirection into ct16; else h16 rows direct.
// r rows ALWAYS rtab[relation_ids[t]] (rtab = rt16 for hop 0, R0h for hop 1).
template<bool FIRST>
__global__ void scatter_upd(const int* __restrict__ head,
                            const int* __restrict__ tail,
                            const int* __restrict__ labels,
                            const int* __restrict__ concept_ids,
                            const int* __restrict__ relation_ids,
                            const __half* __restrict__ ctab,
                            const __half* __restrict__ h16,
                            const __half* __restrict__ rtab,
                            float* __restrict__ upd,
                            float* __restrict__ cnt) {
    const int t = blockIdx.x;
    if (labels[t] == -1) return;
    const int b  = t / MT;
    const size_t rowh = (size_t)b * MC + head[t];
    const size_t rowt = (size_t)b * MC + tail[t];

    const int i = threadIdx.x;                 // 0..127
    const int o = 4 * i;
    float4 hv, tv;
    if (FIRST) {
        hv = ld_half4(ctab + (size_t)concept_ids[rowh] * E_, o);
        tv = ld_half4(ctab + (size_t)concept_ids[rowt] * E_, o);
    } else {
        hv = ld_half4(h16 + rowh * E_, o);
        tv = ld_half4(h16 + rowt * E_, o);
    }
    float4 rv = ld_half4(rtab + (size_t)relation_ids[t] * E_, o);
    float* ut = upd + rowt * E_;
    float* uh = upd + rowh * E_;
    red4(ut + o, hv.x - rv.x, hv.y - rv.y, hv.z - rv.z, hv.w - rv.w);
    red4(uh + o, tv.x - rv.x, tv.y - rv.y, tv.z - rv.z, tv.w - rv.w);
    if (i == 0) {
        atomicAdd(cnt + rowt, 1.0f);
        atomicAdd(cnt + rowh, 1.0f);
    }
}

// ==================== fp16 tensor-core GEMM NT (proven R9 core) ==============
// CTA 128x256, BK=32, double-buffered, 256 threads = 8 warps, 64x64 warp tiles.
template<int NSRC, bool RELU, bool A0HALF, bool CHALF>
__global__ __launch_bounds__(256, 1)
void gemm_fp16(const void* __restrict__ A0v, const int* __restrict__ ids0,
               const __half* __restrict__ Wf0,
               const float* __restrict__ A1, const __half* __restrict__ Wf1,
               const float* __restrict__ cnt,
               void* __restrict__ Cv, int ldc, int coff) {
    constexpr int KT = E_ / 32;                // 16 K-slices per source
    constexpr int TOTAL = NSRC * KT;

    __shared__ __align__(16) char sm[49152];   // As[2]:0,8K  Bs[2]:16K,32K
    const uint32_t sbase = (uint32_t)__cvta_generic_to_shared(sm);

    const int tid  = threadIdx.x;
    const int lane = tid & 31;
    const int wq   = tid >> 5;                 // warp 0..7
    const int wm   = (wq >> 2) * 64;
    const int wn   = (wq & 3) * 64;
    const int bm   = blockIdx.y * 128;
    const int bn   = blockIdx.x * 256;

    // ---- A staging: thread owns 4-elem chunk aj of rows ar+32*i, i=0..3 ----
    const int ar = tid >> 3;                   // 0..31
    const int aj = tid & 7;
    const int adst0 = ar * 64 + (((aj >> 1) ^ ((ar >> 1) & 3)) << 4) + ((aj & 1) << 3);
    const __half* Ah[4]; const float* Af[4]; const float* Au[4];
    float sc[4];
    #pragma unroll
    for (int i = 0; i < 4; ++i) {
        const int gr = bm + ar + 32 * i;
        const int gi = ids0 ? ids0[gr] : gr;
        if (A0HALF) Ah[i] = (const __half*)A0v + (size_t)gi * E_ + aj * 4;
        else        Af[i] = (const float*)A0v + (size_t)gi * E_ + aj * 4;
        if (NSRC == 2) {
            Au[i] = A1 + (size_t)gr * E_ + aj * 4;
            sc[i] = 1.0f / fmaxf(cnt[gr], 1.0f);
        }
    }

    // ---- B staging: 4 x uint4 of the 16KB pre-swizzled slice ----
    const __half* Bt0 = Wf0 + (size_t)blockIdx.x * 16 * 8192 + tid * 8;
    const __half* Bt1 = (NSRC == 2) ? (Wf1 + (size_t)blockIdx.x * 16 * 8192 + tid * 8) : nullptr;

    // ---- ldmatrix fragment offsets ----
    const int mloc  = (lane & 7) + ((lane >> 3) & 1) * 8;
    const int khalf = lane >> 4;
    int aoff[4][2], boff[4][2];
    #pragma unroll
    for (int f = 0; f < 4; ++f) {
        const int row = wm + f * 16 + mloc;
        const int sw  = (row >> 1) & 3;
        #pragma unroll
        for (int kk = 0; kk < 2; ++kk)
            aoff[f][kk] = row * 64 + ((((kk << 1) | khalf) ^ sw) << 4);
    }
    #pragma unroll
    for (int q = 0; q < 4; ++q) {
        const int row = wn + q * 16 + mloc;
        const int sw  = (row >> 1) & 3;
        #pragma unroll
        for (int kk = 0; kk < 2; ++kk)
            boff[q][kk] = row * 64 + ((((kk << 1) | khalf) ^ sw) << 4);
    }

    float4 la[4];
    uint2  lau[4];
    bool   conv = false;
    uint4  lb[4];

    float acc[4][8][4];
    #pragma unroll
    for (int f = 0; f < 4; ++f)
        #pragma unroll
        for (int g = 0; g < 8; ++g)
            #pragma unroll
            for (int e = 0; e < 4; ++e) acc[f][g][e] = 0.0f;

    auto ldg = [&](int t) {
        const bool sec = (NSRC == 2) && (t >= KT);
        const int s = t & (KT - 1);
        if (sec) {
            #pragma unroll
            for (int i = 0; i < 4; ++i) {
                la[i] = *(const float4*)(Au[i] + s * 32);
                la[i].x *= sc[i]; la[i].y *= sc[i];
                la[i].z *= sc[i]; la[i].w *= sc[i];
            }
            conv = true;
        } else if (A0HALF) {
            #pragma unroll
            for (int i = 0; i < 4; ++i) lau[i] = *(const uint2*)(Ah[i] + s * 32);
            conv = false;
        } else {
            #pragma unroll
            for (int i = 0; i < 4; ++i) la[i] = *(const float4*)(Af[i] + s * 32);
            conv = true;
        }
        const __half* bp = (sec ? Bt1 : Bt0) + (size_t)s * 8192;
        #pragma unroll
        for (int q = 0; q < 4; ++q) lb[q] = *(const uint4*)(bp + q * 2048);
    };

    auto sts = [&](int buf) {
        char* ab = sm + buf * 8192;
        #pragma unroll
        for (int i = 0; i < 4; ++i) {
            uint2 v;
            if (conv) {
                v.x = h2u(__floats2half2_rn(la[i].x, la[i].y));
                v.y = h2u(__floats2half2_rn(la[i].z, la[i].w));
            } else {
                v = lau[i];
            }
            *(uint2*)(ab + adst0 + i * 2048) = v;   // +32 rows = +2048 B
        }
        char* bb = sm + 16384 + buf * 16384;
        #pragma unroll
        for (int q = 0; q < 4; ++q)
            *(uint4*)(bb + tid * 16 + q * 4096) = lb[q];
    };

    auto compute = [&](int buf) {
        const uint32_t ab = sbase + buf * 8192;
        const uint32_t bb = sbase + 16384 + buf * 16384;
        #pragma unroll
        for (int kk = 0; kk < 2; ++kk) {
            uint32_t a[4][4];
            #pragma unroll
            for (int f = 0; f < 4; ++f) ldsm4(a[f], ab + aoff[f][kk]);
            #pragma unroll
            for (int q = 0; q < 4; ++q) {
                uint32_t b[4];
                ldsm4(b, bb + boff[q][kk]);
                #pragma unroll
                for (int f = 0; f < 4; ++f) {
                    mma_fp16(acc[f][q * 2 + 0], a[f], b[0], b[2]);
                    mma_fp16(acc[f][q * 2 + 1], a[f], b[1], b[3]);
                }
            }
        }
    };

    // ---- pipeline ----
    ldg(0);
    sts(0);
    __syncthreads();
    for (int t = 0; t < TOTAL; ++t) {
        const int buf = t & 1;
        if (t + 1 < TOTAL) ldg(t + 1);
        compute(buf);
        if (t + 1 < TOTAL) {
            sts(buf ^ 1);
            __syncthreads();
        }
    }

    // ---- epilogue: warp tile 64x64 ----
    #pragma unroll
    for (int f = 0; f < 4; ++f) {
        #pragma unroll
        for (int g = 0; g < 8; ++g) {
            const int row0 = bm + wm + f * 16 + (lane >> 2);
            const int col  = wn + g * 8 + (lane & 3) * 2;
            float2 v0 = make_float2(acc[f][g][0], acc[f][g][1]);
            float2 v1 = make_float2(acc[f][g][2], acc[f][g][3]);
            if (RELU) {
                v0.x = fmaxf(v0.x, 0.f); v0.y = fmaxf(v0.y, 0.f);
                v1.x = fmaxf(v1.x, 0.f); v1.y = fmaxf(v1.y, 0.f);
            }
            if (CHALF) {
                __half* Ch = (__half*)Cv;
                *(uint32_t*)&Ch[(size_t)row0 * E_ + bn + col] =
                    h2u(__floats2half2_rn(v0.x, v0.y));
                *(uint32_t*)&Ch[(size_t)(row0 + 8) * E_ + bn + col] =
                    h2u(__floats2half2_rn(v1.x, v1.y));
            } else {
                float* Cf = (float*)Cv;
                *(float2*)&Cf[(size_t)row0 * ldc + coff + bn + col]       = v0;
                *(float2*)&Cf[(size_t)(row0 + 8) * ldc + coff + bn + col] = v1;
            }
        }
    }
}

// ---------------- out slice 1: out[t][512:1024] = R1[rel_ids[t]] -------------
__global__ void write_rslice(const float* __restrict__ R1,
                             const int* __restrict__ relation_ids,
                             float* __restrict__ out) {
    const int t = blockIdx.x;
    const float4* rr = (const float4*)(R1 + (size_t)relation_ids[t] * E_);
    float4* o = (float4*)(out + (size_t)t * 3 * E_);
    o[128 + threadIdx.x] = rr[threadIdx.x];
}

// ---------------- final: out slices 0 and 2 ----------------------------------
__global__ void final_gather02(const __half* __restrict__ h2,
                               const int* __restrict__ head,
                               const int* __restrict__ tail,
                               float* __restrict__ out) {
    const int t = blockIdx.x;
    const int b = t / MT;
    const __half* hh = h2 + ((size_t)b * MC + head[t]) * E_;
    const __half* ht = h2 + ((size_t)b * MC + tail[t]) * E_;
    float4* o = (float4*)(out + (size_t)t * 3 * E_);
    const int i = threadIdx.x;                 // 0..127
    const int off = 4 * i;
    o[i]       = ld_half4(hh, off);
    o[256 + i] = ld_half4(ht, off);
}

// ---------------- host launch ------------------------------------------------
extern "C" void kernel_launch(void* const* d_in, const int* in_sizes, int n_in,
                              void* d_out, int out_size) {
    const float* concept_table  = (const float*)d_in[0];
    const float* relation_table = (const float*)d_in[1];
    const float* W_s            = (const float*)d_in[2];
    const float* W_n            = (const float*)d_in[3];
    const float* W_r            = (const float*)d_in[4];
    const int*   concept_ids    = (const int*)d_in[5];
    const int*   relation_ids   = (const int*)d_in[6];
    const int*   head_idx       = (const int*)d_in[7];
    const int*   tail_idx       = (const int*)d_in[8];
    const int*   labels         = (const int*)d_in[9];
    float*       out            = (float*)d_out;

    __half *ct16, *rt16, *wr16, *R0h, *h16, *h2h, *wf;
    float *R1f, *upd0, *upd1;
    cudaGetSymbolAddress((void**)&ct16, g_ct16);
    cudaGetSymbolAddress((void**)&rt16, g_rt16);
    cudaGetSymbolAddress((void**)&wr16, g_wr16);
    cudaGetSymbolAddress((void**)&R0h,  g_R0h);
    cudaGetSymbolAddress((void**)&R1f,  g_R1f);
    cudaGetSymbolAddress((void**)&h16,  g_h16);
    cudaGetSymbolAddress((void**)&h2h,  g_h2h);
    cudaGetSymbolAddress((void**)&upd0, g_upd0);
    cudaGetSymbolAddress((void**)&upd1, g_upd1);
    cudaGetSymbolAddress((void**)&wf,   g_wf);
    float* cnt0 = upd0 + (size_t)NROW_H * E_;
    float* cnt1 = upd1 + (size_t)NROW_H * E_;

    cudaStream_t s2;
    cudaStreamCreateWithFlags(&s2, cudaStreamNonBlocking);
    cudaEvent_t eStart, eM0, eRT, ePrepW, eR0, eSide;
    cudaEventCreateWithFlags(&eStart, cudaEventDisableTiming);
    cudaEventCreateWithFlags(&eM0,    cudaEventDisableTiming);
    cudaEventCreateWithFlags(&eRT,    cudaEventDisableTiming);
    cudaEventCreateWithFlags(&ePrepW, cudaEventDisableTiming);
    cudaEventCreateWithFlags(&eR0,    cudaEventDisableTiming);
    cudaEventCreateWithFlags(&eSide,  cudaEventDisableTiming);

    const dim3 gh(E_ / 256, NROW_H / 128);      // (2, 256)
    const size_t UPD_BYTES = sizeof(float) * ((size_t)NROW_H * E_ + NROW_H);

    // ==== side stream ========================================================
    // memset upd0 -> rt16 -> wf -> wr16 -> R0 -> R1 -> out slice 1 -> memset upd1
    cudaEventRecord(eStart, 0);
    cudaStreamWaitEvent(s2, eStart, 0);
    cudaMemsetAsync(upd0, 0, UPD_BYTES, s2);
    cudaEventRecord(eM0, s2);                               // scatter0 gate
    to_half<<<(NREL * E_ / 8 + 255) / 256, 256, 0, s2>>>(relation_table, rt16,
                                                         NREL * E_ / 8);
    cudaEventRecord(eRT, s2);                               // scatter0 gate
    prep_weights<<<4 * MAT / 8 / 256, 256, 0, s2>>>(W_s, W_n, wf);
    cudaEventRecord(ePrepW, s2);                            // hgemm gate
    to_half<<<(2 * MAT / 8 + 255) / 256, 256, 0, s2>>>(W_r, wr16, 2 * MAT / 8);
    small_gemm<true ><<<NREL, 512, 0, s2>>>(rt16, wr16,       R0h, nullptr);
    cudaEventRecord(eR0, s2);                               // scatter1 gate (R0)
    small_gemm<false><<<NREL, 512, 0, s2>>>(R0h,  wr16 + MAT, nullptr, R1f);
    write_rslice<<<NROW_R, 128, 0, s2>>>(R1f, relation_ids, out);
    cudaMemsetAsync(upd1, 0, UPD_BYTES, s2);
    cudaEventRecord(eSide, s2);                             // scatter1 gate (upd1) + join

    // ==== main stream ========================================================
    to_half<<<(VOCAB * E_ / 8 + 255) / 256, 256>>>(concept_table, ct16,
                                                   VOCAB * E_ / 8);
    // hop-0 h-chain
    cudaStreamWaitEvent(0, eM0, 0);
    cudaStreamWaitEvent(0, eRT, 0);
    scatter_upd<true><<<NROW_R, 128>>>(head_idx, tail_idx, labels,
                                       concept_ids, relation_ids,
                                       ct16, nullptr, rt16, upd0, cnt0);
    cudaStreamWaitEvent(0, ePrepW, 0);
    gemm_fp16<2, true, true, true><<<gh, 256>>>(
        ct16, concept_ids, wf + 0 * (size_t)MAT,
        upd0, wf + 2 * (size_t)MAT, cnt0, h16, E_, 0);

    // hop-1 h-chain (needs R0 and cleared upd1 from the side stream)
    cudaStreamWaitEvent(0, eR0, 0);
    cudaStreamWaitEvent(0, eSide, 0);
    scatter_upd<false><<<NROW_R, 128>>>(head_idx, tail_idx, labels,
                                        concept_ids, relation_ids,
                                        nullptr, h16, R0h, upd1, cnt1);
    gemm_fp16<2, true, true, true><<<gh, 256>>>(
        h16, nullptr, wf + 1 * (size_t)MAT,
        upd1, wf + 3 * (size_t)MAT, cnt1, h2h, E_, 0);

    // final: slices 0 and 2 (slice 1 already written by the side stream,
    // whose completion is ordered via the eSide wait above)
    final_gather02<<<NROW_R, 128>>>(h2h, head_idx, tail_idx, out);
}

// round 14
// speedup vs baseline: 1.1833x; 1.1833x over previous
#include <cuda_runtime.h>
#include <cuda_fp16.h>
#include <cstdint>
#include <cstring>

// Problem constants (fixed by the dataset)
#define B_    16
#define MC    2048
#define MT    4096
#define E_    512
#define VOCAB 32000
#define NREL  69

#define NROW_H (B_ * MC)   // 32768
#define NROW_R (B_ * MT)   // 65536
#define MAT    (E_ * E_)   // 262144

// ---------------- scratch (static device globals; no allocation allowed) ---
__device__ __half g_ct16[VOCAB * E_];            // fp16 concept table
__device__ __half g_rt16[NREL * E_];             // fp16 relation table
__device__ __half g_wr16[2 * MAT];               // fp16 plain Wr0, Wr1
__device__ __half g_R0h [NREL * E_];             // r embeddings after hop 0
__device__ float  g_R1f [NREL * E_];             // r embeddings after hop 1
__device__ __half g_h16[NROW_H * E_];            // h after hop 0 (fp16)
__device__ __half g_h2h[NROW_H * E_];            // h after hop 1 (fp16)
__device__ float  g_upd0[NROW_H * E_ + NROW_H];  // hop-0 upd (+cnt tail)
__device__ float  g_upd1[NROW_H * E_ + NROW_H];  // hop-1 upd (+cnt tail)
__device__ __half g_wf [4 * MAT];                // fp16 pre-swizzled weights
                                                 // [Ws0,Ws1,Wn0,Wn1]

// ---------------- bit-cast helper --------------------------------------------
__device__ __forceinline__ uint32_t h2u(__half2 v) {
    uint32_t r;
    memcpy(&r, &v, 4);
    return r;
}

// ---------------- mma / ldmatrix helpers -------------------------------------
__device__ __forceinline__ void ldsm4(uint32_t* r, uint32_t addr) {
    asm volatile("ldmatrix.sync.aligned.m8n8.x4.shared.b16 {%0,%1,%2,%3}, [%4];"
                 : "=r"(r[0]), "=r"(r[1]), "=r"(r[2]), "=r"(r[3]) : "r"(addr));
}

__device__ __forceinline__ void mma_fp16(float* c, const uint32_t* a,
                                         uint32_t b0, uint32_t b1) {
    asm volatile(
        "mma.sync.aligned.m16n8k16.row.col.f32.f16.f16.f32 "
        "{%0,%1,%2,%3}, {%4,%5,%6,%7}, {%8,%9}, {%0,%1,%2,%3};\n"
        : "+f"(c[0]), "+f"(c[1]), "+f"(c[2]), "+f"(c[3])
        : "r"(a[0]), "r"(a[1]), "r"(a[2]), "r"(a[3]), "r"(b0), "r"(b1));
}

// ---------------- fp32 -> fp16 conversion ------------------------------------
__global__ void to_half(const float* __restrict__ src, __half* __restrict__ dst,
                        int n8) {
    const int i = blockIdx.x * 256 + threadIdx.x;   // one 8-elem chunk each
    if (i >= n8) return;
    float4 a = ((const float4*)src)[2 * i];
    float4 b = ((const float4*)src)[2 * i + 1];
    uint4 o;
    o.x = h2u(__floats2half2_rn(a.x, a.y));
    o.y = h2u(__floats2half2_rn(a.z, a.w));
    o.z = h2u(__floats2half2_rn(b.x, b.y));
    o.w = h2u(__floats2half2_rn(b.z, b.w));
    ((uint4*)dst)[i] = o;
}

// ---------------- weight prep: fp32 row-major -> fp16 pre-swizzled tiles ----
// Only Ws0,Ws1,Wn0,Wn1 (the big h-GEMMs). Layout as in prior rounds.
__global__ void prep_weights(const float* __restrict__ Ws,
                             const float* __restrict__ Wn,
                             __half* __restrict__ dst) {
    const int idx = blockIdx.x * 256 + threadIdx.x;   // one 16B unit each
    const int mat  = idx >> 15;                       // 0..3
    const int rem  = idx & 32767;
    const int p    = rem >> 14;
    const int s    = (rem >> 10) & 15;
    const int nl   = (rem >> 2) & 255;
    const int u    = rem & 3;
    const float* src = (mat < 2) ? Ws + (size_t)mat * MAT
                                 : Wn + (size_t)(mat - 2) * MAT;
    const float* sp = src + (size_t)(p * 256 + nl) * E_ + s * 32 + u * 8;
    float4 v0 = ((const float4*)sp)[0];
    float4 v1 = ((const float4*)sp)[1];
    uint4 o;
    o.x = h2u(__floats2half2_rn(v0.x, v0.y));
    o.y = h2u(__floats2half2_rn(v0.z, v0.w));
    o.z = h2u(__floats2half2_rn(v1.x, v1.y));
    o.w = h2u(__floats2half2_rn(v1.z, v1.w));
    const int up = u ^ ((nl >> 1) & 3);
    *(uint4*)(dst + (size_t)mat * MAT + ((p * 16 + s) * 8192) + nl * 32 + up * 8) = o;
}

// ---------------- tiny r-GEMM: out[row][n] = sum_k A[row][k] * W[n][k] -------
// grid (NREL, 4): block (row, 128-col slice), 128 threads = 1 col each.
// fp16 inputs, fp32 accumulate -- same rounding points as the big GEMM path.
template<bool OUT16>
__global__ void __launch_bounds__(128)
small_gemm(const __half* __restrict__ A, const __half* __restrict__ W,
           __half* __restrict__ out16, float* __restrict__ out32) {
    __shared__ float arow[E_];
    const int row = blockIdx.x;
    const int n   = blockIdx.y * 128 + threadIdx.x;
    // load A row cooperatively: 256 half2 across 128 threads (2 each)
    #pragma unroll
    for (int j = 0; j < 2; ++j) {
        const int idx = threadIdx.x * 2 + j;
        float2 f = __half22float2(((const __half2*)(A + (size_t)row * E_))[idx]);
        arow[2 * idx]     = f.x;
        arow[2 * idx + 1] = f.y;
    }
    __syncthreads();
    const __half2* w2 = (const __half2*)(W + (size_t)n * E_);
    float s = 0.0f;
    #pragma unroll 16
    for (int k = 0; k < E_ / 2; ++k) {
        float2 wf = __half22float2(w2[k]);
        s += arow[2 * k] * wf.x + arow[2 * k + 1] * wf.y;
    }
    if (OUT16) out16[(size_t)row * E_ + n] = __float2half_rn(s);
    else       out32[(size_t)row * E_ + n] = s;
}

// ---------------- scatter messages + degree counts (vector red) -------------
__device__ __forceinline__ void red4(float* p, float a, float b, float c, float d) {
    asm volatile("red.global.add.v4.f32 [%0], {%1, %2, %3, %4};"
                 :: "l"(p), "f"(a), "f"(b), "f"(c), "f"(d) : "memory");
}

__device__ __forceinline__ float4 ld_half4(const __half* p, int o) {
    const __half2* q = (const __half2*)(p + o);
    float2 f0 = __half22float2(q[0]);
    float2 f1 = __half22float2(q[1]);
    return make_float4(f0.x, f0.y, f1.x, f1.y);
}

// FIRST: h rows via concept_ids indirection into ct16; else h16 rows direct.
// r rows ALWAYS rtab[relation_ids[t]] (rtab = rt16 for hop 0, R0h for hop 1).
template<bool FIRST>
__global__ void scatter_upd(const int* __restrict__ head,
                            const int* __restrict__ tail,
                            const int* __restrict__ labels,
                            const int* __restrict__ concept_ids,
                            const int* __restrict__ relation_ids,
                            const __half* __restrict__ ctab,
                            const __half* __restrict__ h16,
                            const __half* __restrict__ rtab,
                            float* __restrict__ upd,
                            float* __restrict__ cnt) {
    const int t = blockIdx.x;
    if (labels[t] == -1) return;
    const int b  = t / MT;
    const size_t rowh = (size_t)b * MC + head[t];
    const size_t rowt = (size_t)b * MC + tail[t];

    const int i = threadIdx.x;                 // 0..127
    const int o = 4 * i;
    float4 hv, tv;
    if (FIRST) {
        hv = ld_half4(ctab + (size_t)concept_ids[rowh] * E_, o);
        tv = ld_half4(ctab + (size_t)concept_ids[rowt] * E_, o);
    } else {
        hv = ld_half4(h16 + rowh * E_, o);
        tv = ld_half4(h16 + rowt * E_, o);
    }
    float4 rv = ld_half4(rtab + (size_t)relation_ids[t] * E_, o);
    float* ut = upd + rowt * E_;
    float* uh = upd + rowh * E_;
    red4(ut + o, hv.x - rv.x, hv.y - rv.y, hv.z - rv.z, hv.w - rv.w);
    red4(uh + o, tv.x - rv.x, tv.y - rv.y, tv.z - rv.z, tv.w - rv.w);
    if (i == 0) {
        atomicAdd(cnt + rowt, 1.0f);
        atomicAdd(cnt + rowh, 1.0f);
    }
}

// ==================== fp16 tensor-core GEMM NT (proven R9 core) ==============
// CTA 128x256, BK=32, double-buffered, 256 threads = 8 warps, 64x64 warp tiles.
template<int NSRC, bool RELU, bool A0HALF, bool CHALF>
__global__ __launch_bounds__(256, 1)
void gemm_fp16(const void* __restrict__ A0v, const int* __restrict__ ids0,
               const __half* __restrict__ Wf0,
               const float* __restrict__ A1, const __half* __restrict__ Wf1,
               const float* __restrict__ cnt,
               void* __restrict__ Cv, int ldc, int coff) {
    constexpr int KT = E_ / 32;                // 16 K-slices per source
    constexpr int TOTAL = NSRC * KT;

    __shared__ __align__(16) char sm[49152];   // As[2]:0,8K  Bs[2]:16K,32K
    const uint32_t sbase = (uint32_t)__cvta_generic_to_shared(sm);

    const int tid  = threadIdx.x;
    const int lane = tid & 31;
    const int wq   = tid >> 5;                 // warp 0..7
    const int wm   = (wq >> 2) * 64;
    const int wn   = (wq & 3) * 64;
    const int bm   = blockIdx.y * 128;
    const int bn   = blockIdx.x * 256;

    // ---- A staging: thread owns 4-elem chunk aj of rows ar+32*i, i=0..3 ----
    const int ar = tid >> 3;                   // 0..31
    const int aj = tid & 7;
    const int adst0 = ar * 64 + (((aj >> 1) ^ ((ar >> 1) & 3)) << 4) + ((aj & 1) << 3);
    const __half* Ah[4]; const float* Af[4]; const float* Au[4];
    float sc[4];
    #pragma unroll
    for (int i = 0; i < 4; ++i) {
        const int gr = bm + ar + 32 * i;
        const int gi = ids0 ? ids0[gr] : gr;
        if (A0HALF) Ah[i] = (const __half*)A0v + (size_t)gi * E_ + aj * 4;
        else        Af[i] = (const float*)A0v + (size_t)gi * E_ + aj * 4;
        if (NSRC == 2) {
            Au[i] = A1 + (size_t)gr * E_ + aj * 4;
            sc[i] = 1.0f / fmaxf(cnt[gr], 1.0f);
        }
    }

    // ---- B staging: 4 x uint4 of the 16KB pre-swizzled slice ----
    const __half* Bt0 = Wf0 + (size_t)blockIdx.x * 16 * 8192 + tid * 8;
    const __half* Bt1 = (NSRC == 2) ? (Wf1 + (size_t)blockIdx.x * 16 * 8192 + tid * 8) : nullptr;

    // ---- ldmatrix fragment offsets ----
    const int mloc  = (lane & 7) + ((lane >> 3) & 1) * 8;
    const int khalf = lane >> 4;
    int aoff[4][2], boff[4][2];
    #pragma unroll
    for (int f = 0; f < 4; ++f) {
        const int row = wm + f * 16 + mloc;
        const int sw  = (row >> 1) & 3;
        #pragma unroll
        for (int kk = 0; kk < 2; ++kk)
            aoff[f][kk] = row * 64 + ((((kk << 1) | khalf) ^ sw) << 4);
    }
    #pragma unroll
    for (int q = 0; q < 4; ++q) {
        const int row = wn + q * 16 + mloc;
        const int sw  = (row >> 1) & 3;
        #pragma unroll
        for (int kk = 0; kk < 2; ++kk)
            boff[q][kk] = row * 64 + ((((kk << 1) | khalf) ^ sw) << 4);
    }

    float4 la[4];
    uint2  lau[4];
    bool   conv = false;
    uint4  lb[4];

    float acc[4][8][4];
    #pragma unroll
    for (int f = 0; f < 4; ++f)
        #pragma unroll
        for (int g = 0; g < 8; ++g)
            #pragma unroll
            for (int e = 0; e < 4; ++e) acc[f][g][e] = 0.0f;

    auto ldg = [&](int t) {
        const bool sec = (NSRC == 2) && (t >= KT);
        const int s = t & (KT - 1);
        if (sec) {
            #pragma unroll
            for (int i = 0; i < 4; ++i) {
                la[i] = *(const float4*)(Au[i] + s * 32);
                la[i].x *= sc[i]; la[i].y *= sc[i];
                la[i].z *= sc[i]; la[i].w *= sc[i];
            }
            conv = true;
        } else if (A0HALF) {
            #pragma unroll
            for (int i = 0; i < 4; ++i) lau[i] = *(const uint2*)(Ah[i] + s * 32);
            conv = false;
        } else {
            #pragma unroll
            for (int i = 0; i < 4; ++i) la[i] = *(const float4*)(Af[i] + s * 32);
            conv = true;
        }
        const __half* bp = (sec ? Bt1 : Bt0) + (size_t)s * 8192;
        #pragma unroll
        for (int q = 0; q < 4; ++q) lb[q] = *(const uint4*)(bp + q * 2048);
    };

    auto sts = [&](int buf) {
        char* ab = sm + buf * 8192;
        #pragma unroll
        for (int i = 0; i < 4; ++i) {
            uint2 v;
            if (conv) {
                v.x = h2u(__floats2half2_rn(la[i].x, la[i].y));
                v.y = h2u(__floats2half2_rn(la[i].z, la[i].w));
            } else {
                v = lau[i];
            }
            *(uint2*)(ab + adst0 + i * 2048) = v;   // +32 rows = +2048 B
        }
        char* bb = sm + 16384 + buf * 16384;
        #pragma unroll
        for (int q = 0; q < 4; ++q)
            *(uint4*)(bb + tid * 16 + q * 4096) = lb[q];
    };

    auto compute = [&](int buf) {
        const uint32_t ab = sbase + buf * 8192;
        const uint32_t bb = sbase + 16384 + buf * 16384;
        #pragma unroll
        for (int kk = 0; kk < 2; ++kk) {
            uint32_t a[4][4];
            #pragma unroll
            for (int f = 0; f < 4; ++f) ldsm4(a[f], ab + aoff[f][kk]);
            #pragma unroll
            for (int q = 0; q < 4; ++q) {
                uint32_t b[4];
                ldsm4(b, bb + boff[q][kk]);
                #pragma unroll
                for (int f = 0; f < 4; ++f) {
                    mma_fp16(acc[f][q * 2 + 0], a[f], b[0], b[2]);
                    mma_fp16(acc[f][q * 2 + 1], a[f], b[1], b[3]);
                }
            }
        }
    };

    // ---- pipeline ----
    ldg(0);
    sts(0);
    __syncthreads();
    for (int t = 0; t < TOTAL; ++t) {
        const int buf = t & 1;
        if (t + 1 < TOTAL) ldg(t + 1);
        compute(buf);
        if (t + 1 < TOTAL) {
            sts(buf ^ 1);
            __syncthreads();
        }
    }

    // ---- epilogue: warp tile 64x64 ----
    #pragma unroll
    for (int f = 0; f < 4; ++f) {
        #pragma unroll
        for (int g = 0; g < 8; ++g) {
            const int row0 = bm + wm + f * 16 + (lane >> 2);
            const int col  = wn + g * 8 + (lane & 3) * 2;
            float2 v0 = make_float2(acc[f][g][0], acc[f][g][1]);
            float2 v1 = make_float2(acc[f][g][2], acc[f][g][3]);
            if (RELU) {
                v0.x = fmaxf(v0.x, 0.f); v0.y = fmaxf(v0.y, 0.f);
                v1.x = fmaxf(v1.x, 0.f); v1.y = fmaxf(v1.y, 0.f);
            }
            if (CHALF) {
                __half* Ch = (__half*)Cv;
                *(uint32_t*)&Ch[(size_t)row0 * E_ + bn + col] =
                    h2u(__floats2half2_rn(v0.x, v0.y));
                *(uint32_t*)&Ch[(size_t)(row0 + 8) * E_ + bn + col] =
                    h2u(__floats2half2_rn(v1.x, v1.y));
            } else {
                float* Cf = (float*)Cv;
                *(float2*)&Cf[(size_t)row0 * ldc + coff + bn + col]       = v0;
                *(float2*)&Cf[(size_t)(row0 + 8) * ldc + coff + bn + col] = v1;
            }
        }
    }
}

// ---------------- out slice 1: out[t][512:1024] = R1[rel_ids[t]] -------------
__global__ void write_rslice(const float* __restrict__ R1,
                             const int* __restrict__ relation_ids,
                             float* __restrict__ out) {
    const int t = blockIdx.x;
    const float4* rr = (const float4*)(R1 + (size_t)relation_ids[t] * E_);
    float4* o = (float4*)(out + (size_t)t * 3 * E_);
    o[128 + threadIdx.x] = rr[threadIdx.x];
}

// ---------------- final: out slices 0 and 2 ----------------------------------
__global__ void final_gather02(const __half* __restrict__ h2,
                               const int* __restrict__ head,
                               const int* __restrict__ tail,
                               float* __restrict__ out) {
    const int t = blockIdx.x;
    const int b = t / MT;
    const __half* hh = h2 + ((size_t)b * MC + head[t]) * E_;
    const __half* ht = h2 + ((size_t)b * MC + tail[t]) * E_;
    float4* o = (float4*)(out + (size_t)t * 3 * E_);
    const int i = threadIdx.x;                 // 0..127
    const int off = 4 * i;
    o[i]       = ld_half4(hh, off);
    o[256 + i] = ld_half4(ht, off);
}

// ---------------- host launch ------------------------------------------------
extern "C" void kernel_launch(void* const* d_in, const int* in_sizes, int n_in,
                              void* d_out, int out_size) {
    const float* concept_table  = (const float*)d_in[0];
    const float* relation_table = (const float*)d_in[1];
    const float* W_s            = (const float*)d_in[2];
    const float* W_n            = (const float*)d_in[3];
    const float* W_r            = (const float*)d_in[4];
    const int*   concept_ids    = (const int*)d_in[5];
    const int*   relation_ids   = (const int*)d_in[6];
    const int*   head_idx       = (const int*)d_in[7];
    const int*   tail_idx       = (const int*)d_in[8];
    const int*   labels         = (const int*)d_in[9];
    float*       out            = (float*)d_out;

    __half *ct16, *rt16, *wr16, *R0h, *h16, *h2h, *wf;
    float *R1f, *upd0, *upd1;
    cudaGetSymbolAddress((void**)&ct16, g_ct16);
    cudaGetSymbolAddress((void**)&rt16, g_rt16);
    cudaGetSymbolAddress((void**)&wr16, g_wr16);
    cudaGetSymbolAddress((void**)&R0h,  g_R0h);
    cudaGetSymbolAddress((void**)&R1f,  g_R1f);
    cudaGetSymbolAddress((void**)&h16,  g_h16);
    cudaGetSymbolAddress((void**)&h2h,  g_h2h);
    cudaGetSymbolAddress((void**)&upd0, g_upd0);
    cudaGetSymbolAddress((void**)&upd1, g_upd1);
    cudaGetSymbolAddress((void**)&wf,   g_wf);
    float* cnt0 = upd0 + (size_t)NROW_H * E_;
    float* cnt1 = upd1 + (size_t)NROW_H * E_;

    cudaStream_t s2;
    cudaStreamCreateWithFlags(&s2, cudaStreamNonBlocking);
    cudaEvent_t eStart, eM0, eT16, eR0, eSide;
    cudaEventCreateWithFlags(&eStart, cudaEventDisableTiming);
    cudaEventCreateWithFlags(&eM0,    cudaEventDisableTiming);
    cudaEventCreateWithFlags(&eT16,   cudaEventDisableTiming);
    cudaEventCreateWithFlags(&eR0,    cudaEventDisableTiming);
    cudaEventCreateWithFlags(&eSide,  cudaEventDisableTiming);

    const dim3 gh(E_ / 256, NROW_H / 128);      // (2, 256)
    const dim3 gsmall(NREL, 4);                 // tiny r-GEMM grid
    const size_t UPD_BYTES = sizeof(float) * ((size_t)NROW_H * E_ + NROW_H);

    // ==== side stream (R12 schedule + rslice appended) =======================
    cudaEventRecord(eStart, 0);
    cudaStreamWaitEvent(s2, eStart, 0);
    cudaMemsetAsync(upd0, 0, UPD_BYTES, s2);
    cudaMemsetAsync(upd1, 0, UPD_BYTES, s2);
    cudaEventRecord(eM0, s2);                               // scatter gates

    // ==== main: table + weight prep ==========================================
    to_half<<<(VOCAB * E_ / 8 + 255) / 256, 256>>>(concept_table, ct16, VOCAB * E_ / 8);
    to_half<<<(NREL * E_ / 8 + 255) / 256, 256>>>(relation_table, rt16, NREL * E_ / 8);
    to_half<<<(2 * MAT / 8 + 255) / 256, 256>>>(W_r, wr16, 2 * MAT / 8);
    prep_weights<<<4 * MAT / 8 / 256, 256>>>(W_s, W_n, wf);
    cudaEventRecord(eT16, 0);

    // side stream: R0 = rt16 @ Wr0^T, R1 = R0 @ Wr1^T, then out slice 1
    cudaStreamWaitEvent(s2, eT16, 0);
    small_gemm<true ><<<gsmall, 128, 0, s2>>>(rt16, wr16,       R0h, nullptr);
    cudaEventRecord(eR0, s2);                               // scatter1 gate
    small_gemm<false><<<gsmall, 128, 0, s2>>>(R0h,  wr16 + MAT, nullptr, R1f);
    write_rslice<<<NROW_R, 128, 0, s2>>>(R1f, relation_ids, out);
    cudaEventRecord(eSide, s2);                             // final gate

    // ==== main: hop-0 h-chain =================================================
    cudaStreamWaitEvent(0, eM0, 0);
    scatter_upd<true><<<NROW_R, 128>>>(head_idx, tail_idx, labels,
                                       concept_ids, relation_ids,
                                       ct16, nullptr, rt16, upd0, cnt0);
    gemm_fp16<2, true, true, true><<<gh, 256>>>(
        ct16, concept_ids, wf + 0 * (size_t)MAT,
        upd0, wf + 2 * (size_t)MAT, cnt0, h16, E_, 0);

    // ==== main: hop-1 h-chain (needs R0 from the side stream) ================
    cudaStreamWaitEvent(0, eR0, 0);
    scatter_upd<false><<<NROW_R, 128>>>(head_idx, tail_idx, labels,
                                        concept_ids, relation_ids,
                                        nullptr, h16, R0h, upd1, cnt1);
    gemm_fp16<2, true, true, true><<<gh, 256>>>(
        h16, nullptr, wf + 1 * (size_t)MAT,
        upd1, wf + 3 * (size_t)MAT, cnt1, h2h, E_, 0);

    // ==== final: slices 0 and 2 (slice 1 written by side stream) =============
    cudaStreamWaitEvent(0, eSide, 0);
    final_gather02<<<NROW_R, 128>>>(h2h, head_idx, tail_idx, out);
}

// round 15
// speedup vs baseline: 1.2036x; 1.0171x over previous
#include <cuda_runtime.h>
#include <cuda_fp16.h>
#include <cstdint>
#include <cstring>

// Problem constants (fixed by the dataset)
#define B_    16
#define MC    2048
#define MT    4096
#define E_    512
#define VOCAB 32000
#define NREL  69

#define NROW_H (B_ * MC)   // 32768
#define NROW_R (B_ * MT)   // 65536
#define MAT    (E_ * E_)   // 262144

// ---------------- scratch (static device globals; no allocation allowed) ---
__device__ __half g_ct16[VOCAB * E_];            // fp16 concept table
__device__ __half g_rt16[NREL * E_];             // fp16 relation table
__device__ __half g_wr16[2 * MAT];               // fp16 plain Wr0, Wr1
__device__ __half g_R0h [NREL * E_];             // r embeddings after hop 0
__device__ float  g_R1f [NREL * E_];             // r embeddings after hop 1
__device__ __half g_h16[NROW_H * E_];            // h after hop 0 (fp16)
__device__ __half g_h2h[NROW_H * E_];            // h after hop 1 (fp16)
__device__ __half g_upd0[NROW_H * E_];           // hop-0 upd (fp16 atomics)
__device__ __half g_upd1[NROW_H * E_];           // hop-1 upd (fp16 atomics)
__device__ float  g_cnt [NROW_H];                // degree counts (both hops)
__device__ __half g_wf [4 * MAT];                // fp16 pre-swizzled weights
                                                 // [Ws0,Ws1,Wn0,Wn1]

// ---------------- bit-cast helper --------------------------------------------
__device__ __forceinline__ uint32_t h2u(__half2 v) {
    uint32_t r;
    memcpy(&r, &v, 4);
    return r;
}

// ---------------- mma / ldmatrix helpers -------------------------------------
__device__ __forceinline__ void ldsm4(uint32_t* r, uint32_t addr) {
    asm volatile("ldmatrix.sync.aligned.m8n8.x4.shared.b16 {%0,%1,%2,%3}, [%4];"
                 : "=r"(r[0]), "=r"(r[1]), "=r"(r[2]), "=r"(r[3]) : "r"(addr));
}

__device__ __forceinline__ void mma_fp16(float* c, const uint32_t* a,
                                         uint32_t b0, uint32_t b1) {
    asm volatile(
        "mma.sync.aligned.m16n8k16.row.col.f32.f16.f16.f32 "
        "{%0,%1,%2,%3}, {%4,%5,%6,%7}, {%8,%9}, {%0,%1,%2,%3};\n"
        : "+f"(c[0]), "+f"(c[1]), "+f"(c[2]), "+f"(c[3])
        : "r"(a[0]), "r"(a[1]), "r"(a[2]), "r"(a[3]), "r"(b0), "r"(b1));
}

// ---------------- fp32 -> fp16 conversion ------------------------------------
__global__ void to_half(const float* __restrict__ src, __half* __restrict__ dst,
                        int n8) {
    const int i = blockIdx.x * 256 + threadIdx.x;   // one 8-elem chunk each
    if (i >= n8) return;
    float4 a = ((const float4*)src)[2 * i];
    float4 b = ((const float4*)src)[2 * i + 1];
    uint4 o;
    o.x = h2u(__floats2half2_rn(a.x, a.y));
    o.y = h2u(__floats2half2_rn(a.z, a.w));
    o.z = h2u(__floats2half2_rn(b.x, b.y));
    o.w = h2u(__floats2half2_rn(b.z, b.w));
    ((uint4*)dst)[i] = o;
}

// ---------------- weight prep: fp32 row-major -> fp16 pre-swizzled tiles ----
__global__ void prep_weights(const float* __restrict__ Ws,
                             const float* __restrict__ Wn,
                             __half* __restrict__ dst) {
    const int idx = blockIdx.x * 256 + threadIdx.x;   // one 16B unit each
    const int mat  = idx >> 15;                       // 0..3
    const int rem  = idx & 32767;
    const int p    = rem >> 14;
    const int s    = (rem >> 10) & 15;
    const int nl   = (rem >> 2) & 255;
    const int u    = rem & 3;
    const float* src = (mat < 2) ? Ws + (size_t)mat * MAT
                                 : Wn + (size_t)(mat - 2) * MAT;
    const float* sp = src + (size_t)(p * 256 + nl) * E_ + s * 32 + u * 8;
    float4 v0 = ((const float4*)sp)[0];
    float4 v1 = ((const float4*)sp)[1];
    uint4 o;
    o.x = h2u(__floats2half2_rn(v0.x, v0.y));
    o.y = h2u(__floats2half2_rn(v0.z, v0.w));
    o.z = h2u(__floats2half2_rn(v1.x, v1.y));
    o.w = h2u(__floats2half2_rn(v1.z, v1.w));
    const int up = u ^ ((nl >> 1) & 3);
    *(uint4*)(dst + (size_t)mat * MAT + ((p * 16 + s) * 8192) + nl * 32 + up * 8) = o;
}

// ---------------- tiny r-GEMM: out[row][n] = sum_k A[row][k] * W[n][k] -------
// grid (NREL, 4): block (row, 128-col slice), 128 threads = 1 col each.
template<bool OUT16>
__global__ void __launch_bounds__(128)
small_gemm(const __half* __restrict__ A, const __half* __restrict__ W,
           __half* __restrict__ out16, float* __restrict__ out32) {
    __shared__ float arow[E_];
    const int row = blockIdx.x;
    const int n   = blockIdx.y * 128 + threadIdx.x;
    #pragma unroll
    for (int j = 0; j < 2; ++j) {
        const int idx = threadIdx.x * 2 + j;
        float2 f = __half22float2(((const __half2*)(A + (size_t)row * E_))[idx]);
        arow[2 * idx]     = f.x;
        arow[2 * idx + 1] = f.y;
    }
    __syncthreads();
    const __half2* w2 = (const __half2*)(W + (size_t)n * E_);
    float s = 0.0f;
    #pragma unroll 16
    for (int k = 0; k < E_ / 2; ++k) {
        float2 wf = __half22float2(w2[k]);
        s += arow[2 * k] * wf.x + arow[2 * k + 1] * wf.y;
    }
    if (OUT16) out16[(size_t)row * E_ + n] = __float2half_rn(s);
    else       out32[(size_t)row * E_ + n] = s;
}

// ---------------- scatter messages (+ degree counts on hop 0 only) ----------
__device__ __forceinline__ void red_h2(__half* p, float a, float b) {
    const uint32_t v = h2u(__floats2half2_rn(a, b));
    asm volatile("red.global.add.noftz.f16x2 [%0], %1;"
                 :: "l"(p), "r"(v) : "memory");
}

__device__ __forceinline__ float4 ld_half4(const __half* p, int o) {
    const __half2* q = (const __half2*)(p + o);
    float2 f0 = __half22float2(q[0]);
    float2 f1 = __half22float2(q[1]);
    return make_float4(f0.x, f0.y, f1.x, f1.y);
}

// FIRST: h rows via concept_ids indirection into ct16; else h16 rows direct.
// r rows ALWAYS rtab[relation_ids[t]] (rtab = rt16 for hop 0, R0h for hop 1).
// cnt atomics only on hop 0 (counts are hop-invariant).
template<bool FIRST>
__global__ void scatter_upd(const int* __restrict__ head,
                            const int* __restrict__ tail,
                            const int* __restrict__ labels,
                            const int* __restrict__ concept_ids,
                            const int* __restrict__ relation_ids,
                            const __half* __restrict__ ctab,
                            const __half* __restrict__ h16,
                            const __half* __restrict__ rtab,
                            __half* __restrict__ upd,
                            float* __restrict__ cnt) {
    const int t = blockIdx.x;
    if (labels[t] == -1) return;
    const int b  = t / MT;
    const size_t rowh = (size_t)b * MC + head[t];
    const size_t rowt = (size_t)b * MC + tail[t];

    const int i = threadIdx.x;                 // 0..127
    const int o = 4 * i;
    float4 hv, tv;
    if (FIRST) {
        hv = ld_half4(ctab + (size_t)concept_ids[rowh] * E_, o);
        tv = ld_half4(ctab + (size_t)concept_ids[rowt] * E_, o);
    } else {
        hv = ld_half4(h16 + rowh * E_, o);
        tv = ld_half4(h16 + rowt * E_, o);
    }
    float4 rv = ld_half4(rtab + (size_t)relation_ids[t] * E_, o);
    __half* ut = upd + rowt * E_;
    __half* uh = upd + rowh * E_;
    red_h2(ut + o,     hv.x - rv.x, hv.y - rv.y);
    red_h2(ut + o + 2, hv.z - rv.z, hv.w - rv.w);
    red_h2(uh + o,     tv.x - rv.x, tv.y - rv.y);
    red_h2(uh + o + 2, tv.z - rv.z, tv.w - rv.w);
    if (FIRST && i == 0) {
        atomicAdd(cnt + rowt, 1.0f);
        atomicAdd(cnt + rowh, 1.0f);
    }
}

// ==================== fp16 tensor-core GEMM NT (proven R9 core) ==============
// CTA 128x256, BK=32, double-buffered, 256 threads = 8 warps, 64x64 warp tiles.
// A1 is now fp16 'upd', scaled by 1/clip(cnt,1) at staging (NSRC==2).
template<int NSRC, bool RELU, bool A0HALF, bool CHALF>
__global__ __launch_bounds__(256, 1)
void gemm_fp16(const void* __restrict__ A0v, const int* __restrict__ ids0,
               const __half* __restrict__ Wf0,
               const __half* __restrict__ A1, const __half* __restrict__ Wf1,
               const float* __restrict__ cnt,
               void* __restrict__ Cv, int ldc, int coff) {
    constexpr int KT = E_ / 32;                // 16 K-slices per source
    constexpr int TOTAL = NSRC * KT;

    __shared__ __align__(16) char sm[49152];   // As[2]:0,8K  Bs[2]:16K,32K
    const uint32_t sbase = (uint32_t)__cvta_generic_to_shared(sm);

    const int tid  = threadIdx.x;
    const int lane = tid & 31;
    const int wq   = tid >> 5;                 // warp 0..7
    const int wm   = (wq >> 2) * 64;
    const int wn   = (wq & 3) * 64;
    const int bm   = blockIdx.y * 128;
    const int bn   = blockIdx.x * 256;

    // ---- A staging: thread owns 4-elem chunk aj of rows ar+32*i, i=0..3 ----
    const int ar = tid >> 3;                   // 0..31
    const int aj = tid & 7;
    const int adst0 = ar * 64 + (((aj >> 1) ^ ((ar >> 1) & 3)) << 4) + ((aj & 1) << 3);
    const __half* Ah[4]; const float* Af[4]; const __half* Au[4];
    float sc[4];
    #pragma unroll
    for (int i = 0; i < 4; ++i) {
        const int gr = bm + ar + 32 * i;
        const int gi = ids0 ? ids0[gr] : gr;
        if (A0HALF) Ah[i] = (const __half*)A0v + (size_t)gi * E_ + aj * 4;
        else        Af[i] = (const float*)A0v + (size_t)gi * E_ + aj * 4;
        if (NSRC == 2) {
            Au[i] = A1 + (size_t)gr * E_ + aj * 4;
            sc[i] = 1.0f / fmaxf(cnt[gr], 1.0f);
        }
    }

    // ---- B staging: 4 x uint4 of the 16KB pre-swizzled slice ----
    const __half* Bt0 = Wf0 + (size_t)blockIdx.x * 16 * 8192 + tid * 8;
    const __half* Bt1 = (NSRC == 2) ? (Wf1 + (size_t)blockIdx.x * 16 * 8192 + tid * 8) : nullptr;

    // ---- ldmatrix fragment offsets ----
    const int mloc  = (lane & 7) + ((lane >> 3) & 1) * 8;
    const int khalf = lane >> 4;
    int aoff[4][2], boff[4][2];
    #pragma unroll
    for (int f = 0; f < 4; ++f) {
        const int row = wm + f * 16 + mloc;
        const int sw  = (row >> 1) & 3;
        #pragma unroll
        for (int kk = 0; kk < 2; ++kk)
            aoff[f][kk] = row * 64 + ((((kk << 1) | khalf) ^ sw) << 4);
    }
    #pragma unroll
    for (int q = 0; q < 4; ++q) {
        const int row = wn + q * 16 + mloc;
        const int sw  = (row >> 1) & 3;
        #pragma unroll
        for (int kk = 0; kk < 2; ++kk)
            boff[q][kk] = row * 64 + ((((kk << 1) | khalf) ^ sw) << 4);
    }

    float4 la[4];
    uint2  lau[4];
    bool   conv = false;
    uint4  lb[4];

    float acc[4][8][4];
    #pragma unroll
    for (int f = 0; f < 4; ++f)
        #pragma unroll
        for (int g = 0; g < 8; ++g)
            #pragma unroll
            for (int e = 0; e < 4; ++e) acc[f][g][e] = 0.0f;

    auto ldg = [&](int t) {
        const bool sec = (NSRC == 2) && (t >= KT);
        const int s = t & (KT - 1);
        if (sec) {
            #pragma unroll
            for (int i = 0; i < 4; ++i) {
                float4 v = ld_half4(Au[i], s * 32);
                v.x *= sc[i]; v.y *= sc[i]; v.z *= sc[i]; v.w *= sc[i];
                la[i] = v;
            }
            conv = true;
        } else if (A0HALF) {
            #pragma unroll
            for (int i = 0; i < 4; ++i) lau[i] = *(const uint2*)(Ah[i] + s * 32);
            conv = false;
        } else {
            #pragma unroll
            for (int i = 0; i < 4; ++i) la[i] = *(const float4*)(Af[i] + s * 32);
            conv = true;
        }
        const __half* bp = (sec ? Bt1 : Bt0) + (size_t)s * 8192;
        #pragma unroll
        for (int q = 0; q < 4; ++q) lb[q] = *(const uint4*)(bp + q * 2048);
    };

    auto sts = [&](int buf) {
        char* ab = sm + buf * 8192;
        #pragma unroll
        for (int i = 0; i < 4; ++i) {
            uint2 v;
            if (conv) {
                v.x = h2u(__floats2half2_rn(la[i].x, la[i].y));
                v.y = h2u(__floats2half2_rn(la[i].z, la[i].w));
            } else {
                v = lau[i];
            }
            *(uint2*)(ab + adst0 + i * 2048) = v;   // +32 rows = +2048 B
        }
        char* bb = sm + 16384 + buf * 16384;
        #pragma unroll
        for (int q = 0; q < 4; ++q)
            *(uint4*)(bb + tid * 16 + q * 4096) = lb[q];
    };

    auto compute = [&](int buf) {
        const uint32_t ab = sbase + buf * 8192;
        const uint32_t bb = sbase + 16384 + buf * 16384;
        #pragma unroll
        for (int kk = 0; kk < 2; ++kk) {
            uint32_t a[4][4];
            #pragma unroll
            for (int f = 0; f < 4; ++f) ldsm4(a[f], ab + aoff[f][kk]);
            #pragma unroll
            for (int q = 0; q < 4; ++q) {
                uint32_t b[4];
                ldsm4(b, bb + boff[q][kk]);
                #pragma unroll
                for (int f = 0; f < 4; ++f) {
                    mma_fp16(acc[f][q * 2 + 0], a[f], b[0], b[2]);
                    mma_fp16(acc[f][q * 2 + 1], a[f], b[1], b[3]);
                }
            }
        }
    };

    // ---- pipeline ----
    ldg(0);
    sts(0);
    __syncthreads();
    for (int t = 0; t < TOTAL; ++t) {
        const int buf = t & 1;
        if (t + 1 < TOTAL) ldg(t + 1);
        compute(buf);
        if (t + 1 < TOTAL) {
            sts(buf ^ 1);
            __syncthreads();
        }
    }

    // ---- epilogue: warp tile 64x64 ----
    #pragma unroll
    for (int f = 0; f < 4; ++f) {
        #pragma unroll
        for (int g = 0; g < 8; ++g) {
            const int row0 = bm + wm + f * 16 + (lane >> 2);
            const int col  = wn + g * 8 + (lane & 3) * 2;
            float2 v0 = make_float2(acc[f][g][0], acc[f][g][1]);
            float2 v1 = make_float2(acc[f][g][2], acc[f][g][3]);
            if (RELU) {
                v0.x = fmaxf(v0.x, 0.f); v0.y = fmaxf(v0.y, 0.f);
                v1.x = fmaxf(v1.x, 0.f); v1.y = fmaxf(v1.y, 0.f);
            }
            if (CHALF) {
                __half* Ch = (__half*)Cv;
                *(uint32_t*)&Ch[(size_t)row0 * E_ + bn + col] =
                    h2u(__floats2half2_rn(v0.x, v0.y));
                *(uint32_t*)&Ch[(size_t)(row0 + 8) * E_ + bn + col] =
                    h2u(__floats2half2_rn(v1.x, v1.y));
            } else {
                float* Cf = (float*)Cv;
                *(float2*)&Cf[(size_t)row0 * ldc + coff + bn + col]       = v0;
                *(float2*)&Cf[(size_t)(row0 + 8) * ldc + coff + bn + col] = v1;
            }
        }
    }
}

// ---------------- out slice 1: out[t][512:1024] = R1[rel_ids[t]] -------------
__global__ void write_rslice(const float* __restrict__ R1,
                             const int* __restrict__ relation_ids,
                             float* __restrict__ out) {
    const int t = blockIdx.x;
    const float4* rr = (const float4*)(R1 + (size_t)relation_ids[t] * E_);
    float4* o = (float4*)(out + (size_t)t * 3 * E_);
    o[128 + threadIdx.x] = rr[threadIdx.x];
}

// ---------------- final: out slices 0 and 2 ----------------------------------
__global__ void final_gather02(const __half* __restrict__ h2,
                               const int* __restrict__ head,
                               const int* __restrict__ tail,
                               float* __restrict__ out) {
    const int t = blockIdx.x;
    const int b = t / MT;
    const __half* hh = h2 + ((size_t)b * MC + head[t]) * E_;
    const __half* ht = h2 + ((size_t)b * MC + tail[t]) * E_;
    float4* o = (float4*)(out + (size_t)t * 3 * E_);
    const int i = threadIdx.x;                 // 0..127
    const int off = 4 * i;
    o[i]       = ld_half4(hh, off);
    o[256 + i] = ld_half4(ht, off);
}

// ---------------- host launch ------------------------------------------------
extern "C" void kernel_launch(void* const* d_in, const int* in_sizes, int n_in,
                              void* d_out, int out_size) {
    const float* concept_table  = (const float*)d_in[0];
    const float* relation_table = (const float*)d_in[1];
    const float* W_s            = (const float*)d_in[2];
    const float* W_n            = (const float*)d_in[3];
    const float* W_r            = (const float*)d_in[4];
    const int*   concept_ids    = (const int*)d_in[5];
    const int*   relation_ids   = (const int*)d_in[6];
    const int*   head_idx       = (const int*)d_in[7];
    const int*   tail_idx       = (const int*)d_in[8];
    const int*   labels         = (const int*)d_in[9];
    float*       out            = (float*)d_out;

    __half *ct16, *rt16, *wr16, *R0h, *h16, *h2h, *upd0, *upd1, *wf;
    float *R1f, *cnt;
    cudaGetSymbolAddress((void**)&ct16, g_ct16);
    cudaGetSymbolAddress((void**)&rt16, g_rt16);
    cudaGetSymbolAddress((void**)&wr16, g_wr16);
    cudaGetSymbolAddress((void**)&R0h,  g_R0h);
    cudaGetSymbolAddress((void**)&R1f,  g_R1f);
    cudaGetSymbolAddress((void**)&h16,  g_h16);
    cudaGetSymbolAddress((void**)&h2h,  g_h2h);
    cudaGetSymbolAddress((void**)&upd0, g_upd0);
    cudaGetSymbolAddress((void**)&upd1, g_upd1);
    cudaGetSymbolAddress((void**)&cnt,  g_cnt);
    cudaGetSymbolAddress((void**)&wf,   g_wf);

    cudaStream_t s2;
    cudaStreamCreateWithFlags(&s2, cudaStreamNonBlocking);
    cudaEvent_t eStart, eM0, ePrepW, eR0, eSide;
    cudaEventCreateWithFlags(&eStart, cudaEventDisableTiming);
    cudaEventCreateWithFlags(&eM0,    cudaEventDisableTiming);
    cudaEventCreateWithFlags(&ePrepW, cudaEventDisableTiming);
    cudaEventCreateWithFlags(&eR0,    cudaEventDisableTiming);
    cudaEventCreateWithFlags(&eSide,  cudaEventDisableTiming);

    const dim3 gh(E_ / 256, NROW_H / 128);      // (2, 256)
    const dim3 gsmall(NREL, 4);                 // tiny r-GEMM grid
    const size_t UPD_BYTES = sizeof(__half) * (size_t)NROW_H * E_;

    // ==== side stream: memsets, weight preps, tiny r-chain, out slice 1 ======
    cudaEventRecord(eStart, 0);
    cudaStreamWaitEvent(s2, eStart, 0);
    cudaMemsetAsync(upd0, 0, UPD_BYTES, s2);
    cudaMemsetAsync(upd1, 0, UPD_BYTES, s2);
    cudaMemsetAsync(cnt,  0, sizeof(float) * NROW_H, s2);
    cudaEventRecord(eM0, s2);                               // scatter gates
    prep_weights<<<4 * MAT / 8 / 256, 256, 0, s2>>>(W_s, W_n, wf);
    cudaEventRecord(ePrepW, s2);                            // hgemm gate
    to_half<<<(2 * MAT / 8 + 255) / 256, 256, 0, s2>>>(W_r, wr16, 2 * MAT / 8);
    // rt16 is produced on the MAIN stream before scatter0; the side stream's
    // small_gemm needs it too -> gate via event from main (eRT below).
    cudaEventRecord(eSide, s2);   // placeholder ordering point (re-recorded later)

    // ==== main: table conversions (scatter0 needs ct16 + rt16 only) ==========
    to_half<<<(VOCAB * E_ / 8 + 255) / 256, 256>>>(concept_table, ct16, VOCAB * E_ / 8);
    to_half<<<(NREL * E_ / 8 + 255) / 256, 256>>>(relation_table, rt16, NREL * E_ / 8);
    cudaEvent_t eRT;
    cudaEventCreateWithFlags(&eRT, cudaEventDisableTiming);
    cudaEventRecord(eRT, 0);

    // side stream: tiny r-chain (needs rt16 from main, wr16 local)
    cudaStreamWaitEvent(s2, eRT, 0);
    small_gemm<true ><<<gsmall, 128, 0, s2>>>(rt16, wr16,       R0h, nullptr);
    cudaEventRecord(eR0, s2);                               // scatter1 gate
    small_gemm<false><<<gsmall, 128, 0, s2>>>(R0h,  wr16 + MAT, nullptr, R1f);
    write_rslice<<<NROW_R, 128, 0, s2>>>(R1f, relation_ids, out);
    cudaEventRecord(eSide, s2);                             // final gate

    // ==== main: hop-0 h-chain =================================================
    cudaStreamWaitEvent(0, eM0, 0);
    scatter_upd<true><<<NROW_R, 128>>>(head_idx, tail_idx, labels,
                                       concept_ids, relation_ids,
                                       ct16, nullptr, rt16, upd0, cnt);
    cudaStreamWaitEvent(0, ePrepW, 0);
    gemm_fp16<2, true, true, true><<<gh, 256>>>(
        ct16, concept_ids, wf + 0 * (size_t)MAT,
        upd0, wf + 2 * (size_t)MAT, cnt, h16, E_, 0);

    // ==== main: hop-1 h-chain (needs R0 from the side stream) ================
    cudaStreamWaitEvent(0, eR0, 0);
    scatter_upd<false><<<NROW_R, 128>>>(head_idx, tail_idx, labels,
                                        concept_ids, relation_ids,
                                        nullptr, h16, R0h, upd1, cnt);
    gemm_fp16<2, true, true, true><<<gh, 256>>>(
        h16, nullptr, wf + 1 * (size_t)MAT,
        upd1, wf + 3 * (size_t)MAT, cnt, h2h, E_, 0);

    // ==== final: slices 0 and 2 (slice 1 written by side stream) =============
    cudaStreamWaitEvent(0, eSide, 0);
    final_gather02<<<NROW_R, 128>>>(h2h, head_idx, tail_idx, out);
}

// round 16
// speedup vs baseline: 1.3264x; 1.1020x over previous
#include <cuda_runtime.h>
#include <cuda_fp16.h>
#include <cstdint>
#include <cstring>

// Problem constants (fixed by the dataset)
#define B_    16
#define MC    2048
#define MT    4096
#define E_    512
#define VOCAB 32000
#define NREL  69

#define NROW_H (B_ * MC)   // 32768
#define NROW_R (B_ * MT)   // 65536
#define MAT    (E_ * E_)   // 262144

// ---------------- scratch (static device globals; no allocation allowed) ---
__device__ __half g_ct16[VOCAB * E_];            // fp16 concept table
__device__ __half g_rt16[NREL * E_];             // fp16 relation table
__device__ __half g_wr16[2 * MAT];               // fp16 plain Wr0, Wr1
__device__ __half g_R0h [NREL * E_];             // r embeddings after hop 0
__device__ float  g_R1f [NREL * E_];             // r embeddings after hop 1
__device__ __half g_h16[NROW_H * E_];            // h after hop 0 (fp16)
__device__ __half g_h2h[NROW_H * E_];            // h after hop 1 (fp16)
__device__ __half g_upd0[NROW_H * E_];           // hop-0 upd (fp16 atomics)
__device__ __half g_upd1[NROW_H * E_];           // hop-1 upd (fp16 atomics)
__device__ float  g_cnt [NROW_H];                // degree counts (both hops)
__device__ __half g_wf [4 * MAT];                // fp16 pre-swizzled weights
                                                 // [Ws0,Ws1,Wn0,Wn1]

// ---------------- bit-cast helper --------------------------------------------
__device__ __forceinline__ uint32_t h2u(__half2 v) {
    uint32_t r;
    memcpy(&r, &v, 4);
    return r;
}

// ---------------- mma / ldmatrix helpers -------------------------------------
__device__ __forceinline__ void ldsm4(uint32_t* r, uint32_t addr) {
    asm volatile("ldmatrix.sync.aligned.m8n8.x4.shared.b16 {%0,%1,%2,%3}, [%4];"
                 : "=r"(r[0]), "=r"(r[1]), "=r"(r[2]), "=r"(r[3]) : "r"(addr));
}

__device__ __forceinline__ void mma_fp16(float* c, const uint32_t* a,
                                         uint32_t b0, uint32_t b1) {
    asm volatile(
        "mma.sync.aligned.m16n8k16.row.col.f32.f16.f16.f32 "
        "{%0,%1,%2,%3}, {%4,%5,%6,%7}, {%8,%9}, {%0,%1,%2,%3};\n"
        : "+f"(c[0]), "+f"(c[1]), "+f"(c[2]), "+f"(c[3])
        : "r"(a[0]), "r"(a[1]), "r"(a[2]), "r"(a[3]), "r"(b0), "r"(b1));
}

// ---------------- fp32 -> fp16 conversion ------------------------------------
__global__ void to_half(const float* __restrict__ src, __half* __restrict__ dst,
                        int n8) {
    const int i = blockIdx.x * 256 + threadIdx.x;   // one 8-elem chunk each
    if (i >= n8) return;
    float4 a = ((const float4*)src)[2 * i];
    float4 b = ((const float4*)src)[2 * i + 1];
    uint4 o;
    o.x = h2u(__floats2half2_rn(a.x, a.y));
    o.y = h2u(__floats2half2_rn(a.z, a.w));
    o.z = h2u(__floats2half2_rn(b.x, b.y));
    o.w = h2u(__floats2half2_rn(b.z, b.w));
    ((uint4*)dst)[i] = o;
}

// ---------------- weight prep: fp32 row-major -> fp16 pre-swizzled tiles ----
__global__ void prep_weights(const float* __restrict__ Ws,
                             const float* __restrict__ Wn,
                             __half* __restrict__ dst) {
    const int idx = blockIdx.x * 256 + threadIdx.x;   // one 16B unit each
    const int mat  = idx >> 15;                       // 0..3
    const int rem  = idx & 32767;
    const int p    = rem >> 14;
    const int s    = (rem >> 10) & 15;
    const int nl   = (rem >> 2) & 255;
    const int u    = rem & 3;
    const float* src = (mat < 2) ? Ws + (size_t)mat * MAT
                                 : Wn + (size_t)(mat - 2) * MAT;
    const float* sp = src + (size_t)(p * 256 + nl) * E_ + s * 32 + u * 8;
    float4 v0 = ((const float4*)sp)[0];
    float4 v1 = ((const float4*)sp)[1];
    uint4 o;
    o.x = h2u(__floats2half2_rn(v0.x, v0.y));
    o.y = h2u(__floats2half2_rn(v0.z, v0.w));
    o.z = h2u(__floats2half2_rn(v1.x, v1.y));
    o.w = h2u(__floats2half2_rn(v1.z, v1.w));
    const int up = u ^ ((nl >> 1) & 3);
    *(uint4*)(dst + (size_t)mat * MAT + ((p * 16 + s) * 8192) + nl * 32 + up * 8) = o;
}

// ---------------- tiny r-GEMM: out[row][n] = sum_k A[row][k] * W[n][k] -------
// grid (NREL, 4): block (row, 128-col slice), 128 threads = 1 col each.
template<bool OUT16>
__global__ void __launch_bounds__(128)
small_gemm(const __half* __restrict__ A, const __half* __restrict__ W,
           __half* __restrict__ out16, float* __restrict__ out32) {
    __shared__ float arow[E_];
    const int row = blockIdx.x;
    const int n   = blockIdx.y * 128 + threadIdx.x;
    #pragma unroll
    for (int j = 0; j < 2; ++j) {
        const int idx = threadIdx.x * 2 + j;
        float2 f = __half22float2(((const __half2*)(A + (size_t)row * E_))[idx]);
        arow[2 * idx]     = f.x;
        arow[2 * idx + 1] = f.y;
    }
    __syncthreads();
    const __half2* w2 = (const __half2*)(W + (size_t)n * E_);
    float s = 0.0f;
    #pragma unroll 16
    for (int k = 0; k < E_ / 2; ++k) {
        float2 wf = __half22float2(w2[k]);
        s += arow[2 * k] * wf.x + arow[2 * k + 1] * wf.y;
    }
    if (OUT16) out16[(size_t)row * E_ + n] = __float2half_rn(s);
    else       out32[(size_t)row * E_ + n] = s;
}

// ---------------- scatter messages (+ degree counts on hop 0 only) ----------
__device__ __forceinline__ void red_h2(__half* p, float a, float b) {
    const uint32_t v = h2u(__floats2half2_rn(a, b));
    asm volatile("red.global.add.noftz.f16x2 [%0], %1;"
                 :: "l"(p), "r"(v) : "memory");
}

__device__ __forceinline__ float4 ld_half4(const __half* p, int o) {
    const __half2* q = (const __half2*)(p + o);
    float2 f0 = __half22float2(q[0]);
    float2 f1 = __half22float2(q[1]);
    return make_float4(f0.x, f0.y, f1.x, f1.y);
}

// FIRST: h/r rows read straight from the fp32 tables (double indirection for h).
// Otherwise: h16 rows direct, r rows from fp16 R0h. cnt atomics on hop 0 only.
template<bool FIRST>
__global__ void scatter_upd(const int* __restrict__ head,
                            const int* __restrict__ tail,
                            const int* __restrict__ labels,
                            const int* __restrict__ concept_ids,
                            const int* __restrict__ relation_ids,
                            const float* __restrict__ ctabf,
                            const float* __restrict__ rtabf,
                            const __half* __restrict__ h16,
                            const __half* __restrict__ rtab16,
                            __half* __restrict__ upd,
                            float* __restrict__ cnt) {
    const int t = blockIdx.x;
    if (labels[t] == -1) return;
    const int b  = t / MT;
    const size_t rowh = (size_t)b * MC + head[t];
    const size_t rowt = (size_t)b * MC + tail[t];

    const int i = threadIdx.x;                 // 0..127
    const int o = 4 * i;
    float4 hv, tv, rv;
    if (FIRST) {
        hv = ((const float4*)(ctabf + (size_t)concept_ids[rowh] * E_))[i];
        tv = ((const float4*)(ctabf + (size_t)concept_ids[rowt] * E_))[i];
        rv = ((const float4*)(rtabf + (size_t)relation_ids[t] * E_))[i];
    } else {
        hv = ld_half4(h16 + rowh * E_, o);
        tv = ld_half4(h16 + rowt * E_, o);
        rv = ld_half4(rtab16 + (size_t)relation_ids[t] * E_, o);
    }
    __half* ut = upd + rowt * E_;
    __half* uh = upd + rowh * E_;
    red_h2(ut + o,     hv.x - rv.x, hv.y - rv.y);
    red_h2(ut + o + 2, hv.z - rv.z, hv.w - rv.w);
    red_h2(uh + o,     tv.x - rv.x, tv.y - rv.y);
    red_h2(uh + o + 2, tv.z - rv.z, tv.w - rv.w);
    if (FIRST && i == 0) {
        atomicAdd(cnt + rowt, 1.0f);
        atomicAdd(cnt + rowh, 1.0f);
    }
}

// ==================== fp16 tensor-core GEMM NT (proven core) =================
// CTA 128x256, BK=32, double-buffered, 256 threads = 8 warps, 64x64 warp tiles.
template<int NSRC, bool RELU, bool A0HALF, bool CHALF>
__global__ __launch_bounds__(256, 1)
void gemm_fp16(const void* __restrict__ A0v, const int* __restrict__ ids0,
               const __half* __restrict__ Wf0,
               const __half* __restrict__ A1, const __half* __restrict__ Wf1,
               const float* __restrict__ cnt,
               void* __restrict__ Cv, int ldc, int coff) {
    constexpr int KT = E_ / 32;                // 16 K-slices per source
    constexpr int TOTAL = NSRC * KT;

    __shared__ __align__(16) char sm[49152];   // As[2]:0,8K  Bs[2]:16K,32K
    const uint32_t sbase = (uint32_t)__cvta_generic_to_shared(sm);

    const int tid  = threadIdx.x;
    const int lane = tid & 31;
    const int wq   = tid >> 5;                 // warp 0..7
    const int wm   = (wq >> 2) * 64;
    const int wn   = (wq & 3) * 64;
    const int bm   = blockIdx.y * 128;
    const int bn   = blockIdx.x * 256;

    // ---- A staging: thread owns 4-elem chunk aj of rows ar+32*i, i=0..3 ----
    const int ar = tid >> 3;                   // 0..31
    const int aj = tid & 7;
    const int adst0 = ar * 64 + (((aj >> 1) ^ ((ar >> 1) & 3)) << 4) + ((aj & 1) << 3);
    const __half* Ah[4]; const float* Af[4]; const __half* Au[4];
    float sc[4];
    #pragma unroll
    for (int i = 0; i < 4; ++i) {
        const int gr = bm + ar + 32 * i;
        const int gi = ids0 ? ids0[gr] : gr;
        if (A0HALF) Ah[i] = (const __half*)A0v + (size_t)gi * E_ + aj * 4;
        else        Af[i] = (const float*)A0v + (size_t)gi * E_ + aj * 4;
        if (NSRC == 2) {
            Au[i] = A1 + (size_t)gr * E_ + aj * 4;
            sc[i] = 1.0f / fmaxf(cnt[gr], 1.0f);
        }
    }

    // ---- B staging: 4 x uint4 of the 16KB pre-swizzled slice ----
    const __half* Bt0 = Wf0 + (size_t)blockIdx.x * 16 * 8192 + tid * 8;
    const __half* Bt1 = (NSRC == 2) ? (Wf1 + (size_t)blockIdx.x * 16 * 8192 + tid * 8) : nullptr;

    // ---- ldmatrix fragment offsets ----
    const int mloc  = (lane & 7) + ((lane >> 3) & 1) * 8;
    const int khalf = lane >> 4;
    int aoff[4][2], boff[4][2];
    #pragma unroll
    for (int f = 0; f < 4; ++f) {
        const int row = wm + f * 16 + mloc;
        const int sw  = (row >> 1) & 3;
        #pragma unroll
        for (int kk = 0; kk < 2; ++kk)
            aoff[f][kk] = row * 64 + ((((kk << 1) | khalf) ^ sw) << 4);
    }
    #pragma unroll
    for (int q = 0; q < 4; ++q) {
        const int row = wn + q * 16 + mloc;
        const int sw  = (row >> 1) & 3;
        #pragma unroll
        for (int kk = 0; kk < 2; ++kk)
            boff[q][kk] = row * 64 + ((((kk << 1) | khalf) ^ sw) << 4);
    }

    float4 la[4];
    uint2  lau[4];
    bool   conv = false;
    uint4  lb[4];

    float acc[4][8][4];
    #pragma unroll
    for (int f = 0; f < 4; ++f)
        #pragma unroll
        for (int g = 0; g < 8; ++g)
            #pragma unroll
            for (int e = 0; e < 4; ++e) acc[f][g][e] = 0.0f;

    auto ldg = [&](int t) {
        const bool sec = (NSRC == 2) && (t >= KT);
        const int s = t & (KT - 1);
        if (sec) {
            #pragma unroll
            for (int i = 0; i < 4; ++i) {
                float4 v = ld_half4(Au[i], s * 32);
                v.x *= sc[i]; v.y *= sc[i]; v.z *= sc[i]; v.w *= sc[i];
                la[i] = v;
            }
            conv = true;
        } else if (A0HALF) {
            #pragma unroll
            for (int i = 0; i < 4; ++i) lau[i] = *(const uint2*)(Ah[i] + s * 32);
            conv = false;
        } else {
            #pragma unroll
            for (int i = 0; i < 4; ++i) la[i] = *(const float4*)(Af[i] + s * 32);
            conv = true;
        }
        const __half* bp = (sec ? Bt1 : Bt0) + (size_t)s * 8192;
        #pragma unroll
        for (int q = 0; q < 4; ++q) lb[q] = *(const uint4*)(bp + q * 2048);
    };

    auto sts = [&](int buf) {
        char* ab = sm + buf * 8192;
        #pragma unroll
        for (int i = 0; i < 4; ++i) {
            uint2 v;
            if (conv) {
                v.x = h2u(__floats2half2_rn(la[i].x, la[i].y));
                v.y = h2u(__floats2half2_rn(la[i].z, la[i].w));
            } else {
                v = lau[i];
            }
            *(uint2*)(ab + adst0 + i * 2048) = v;   // +32 rows = +2048 B
        }
        char* bb = sm + 16384 + buf * 16384;
        #pragma unroll
        for (int q = 0; q < 4; ++q)
            *(uint4*)(bb + tid * 16 + q * 4096) = lb[q];
    };

    auto compute = [&](int buf) {
        const uint32_t ab = sbase + buf * 8192;
        const uint32_t bb = sbase + 16384 + buf * 16384;
        #pragma unroll
        for (int kk = 0; kk < 2; ++kk) {
            uint32_t a[4][4];
            #pragma unroll
            for (int f = 0; f < 4; ++f) ldsm4(a[f], ab + aoff[f][kk]);
            #pragma unroll
            for (int q = 0; q < 4; ++q) {
                uint32_t b[4];
                ldsm4(b, bb + boff[q][kk]);
                #pragma unroll
                for (int f = 0; f < 4; ++f) {
                    mma_fp16(acc[f][q * 2 + 0], a[f], b[0], b[2]);
                    mma_fp16(acc[f][q * 2 + 1], a[f], b[1], b[3]);
                }
            }
        }
    };

    // ---- pipeline ----
    ldg(0);
    sts(0);
    __syncthreads();
    for (int t = 0; t < TOTAL; ++t) {
        const int buf = t & 1;
        if (t + 1 < TOTAL) ldg(t + 1);
        compute(buf);
        if (t + 1 < TOTAL) {
            sts(buf ^ 1);
            __syncthreads();
        }
    }

    // ---- epilogue: warp tile 64x64 ----
    #pragma unroll
    for (int f = 0; f < 4; ++f) {
        #pragma unroll
        for (int g = 0; g < 8; ++g) {
            const int row0 = bm + wm + f * 16 + (lane >> 2);
            const int col  = wn + g * 8 + (lane & 3) * 2;
            float2 v0 = make_float2(acc[f][g][0], acc[f][g][1]);
            float2 v1 = make_float2(acc[f][g][2], acc[f][g][3]);
            if (RELU) {
                v0.x = fmaxf(v0.x, 0.f); v0.y = fmaxf(v0.y, 0.f);
                v1.x = fmaxf(v1.x, 0.f); v1.y = fmaxf(v1.y, 0.f);
            }
            if (CHALF) {
                __half* Ch = (__half*)Cv;
                *(uint32_t*)&Ch[(size_t)row0 * E_ + bn + col] =
                    h2u(__floats2half2_rn(v0.x, v0.y));
                *(uint32_t*)&Ch[(size_t)(row0 + 8) * E_ + bn + col] =
                    h2u(__floats2half2_rn(v1.x, v1.y));
            } else {
                float* Cf = (float*)Cv;
                *(float2*)&Cf[(size_t)row0 * ldc + coff + bn + col]       = v0;
                *(float2*)&Cf[(size_t)(row0 + 8) * ldc + coff + bn + col] = v1;
            }
        }
    }
}

// ---------------- out slice 1: out[t][512:1024] = R1[rel_ids[t]] -------------
__global__ void write_rslice(const float* __restrict__ R1,
                             const int* __restrict__ relation_ids,
                             float* __restrict__ out) {
    const int t = blockIdx.x;
    const float4* rr = (const float4*)(R1 + (size_t)relation_ids[t] * E_);
    float4* o = (float4*)(out + (size_t)t * 3 * E_);
    o[128 + threadIdx.x] = rr[threadIdx.x];
}

// ---------------- final: out slices 0 and 2 ----------------------------------
__global__ void final_gather02(const __half* __restrict__ h2,
                               const int* __restrict__ head,
                               const int* __restrict__ tail,
                               float* __restrict__ out) {
    const int t = blockIdx.x;
    const int b = t / MT;
    const __half* hh = h2 + ((size_t)b * MC + head[t]) * E_;
    const __half* ht = h2 + ((size_t)b * MC + tail[t]) * E_;
    float4* o = (float4*)(out + (size_t)t * 3 * E_);
    const int i = threadIdx.x;                 // 0..127
    const int off = 4 * i;
    o[i]       = ld_half4(hh, off);
    o[256 + i] = ld_half4(ht, off);
}

// ---------------- host launch ------------------------------------------------
extern "C" void kernel_launch(void* const* d_in, const int* in_sizes, int n_in,
                              void* d_out, int out_size) {
    const float* concept_table  = (const float*)d_in[0];
    const float* relation_table = (const float*)d_in[1];
    const float* W_s            = (const float*)d_in[2];
    const float* W_n            = (const float*)d_in[3];
    const float* W_r            = (const float*)d_in[4];
    const int*   concept_ids    = (const int*)d_in[5];
    const int*   relation_ids   = (const int*)d_in[6];
    const int*   head_idx       = (const int*)d_in[7];
    const int*   tail_idx       = (const int*)d_in[8];
    const int*   labels         = (const int*)d_in[9];
    float*       out            = (float*)d_out;

    __half *ct16, *rt16, *wr16, *R0h, *h16, *h2h, *upd0, *upd1, *wf;
    float *R1f, *cnt;
    cudaGetSymbolAddress((void**)&ct16, g_ct16);
    cudaGetSymbolAddress((void**)&rt16, g_rt16);
    cudaGetSymbolAddress((void**)&wr16, g_wr16);
    cudaGetSymbolAddress((void**)&R0h,  g_R0h);
    cudaGetSymbolAddress((void**)&R1f,  g_R1f);
    cudaGetSymbolAddress((void**)&h16,  g_h16);
    cudaGetSymbolAddress((void**)&h2h,  g_h2h);
    cudaGetSymbolAddress((void**)&upd0, g_upd0);
    cudaGetSymbolAddress((void**)&upd1, g_upd1);
    cudaGetSymbolAddress((void**)&cnt,  g_cnt);
    cudaGetSymbolAddress((void**)&wf,   g_wf);

    cudaStream_t s2;
    cudaStreamCreateWithFlags(&s2, cudaStreamNonBlocking);
    cudaEvent_t eStart, eM0, eCT, ePrepW, eR0, eSide;
    cudaEventCreateWithFlags(&eStart, cudaEventDisableTiming);
    cudaEventCreateWithFlags(&eM0,    cudaEventDisableTiming);
    cudaEventCreateWithFlags(&eCT,    cudaEventDisableTiming);
    cudaEventCreateWithFlags(&ePrepW, cudaEventDisableTiming);
    cudaEventCreateWithFlags(&eR0,    cudaEventDisableTiming);
    cudaEventCreateWithFlags(&eSide,  cudaEventDisableTiming);

    const dim3 gh(E_ / 256, NROW_H / 128);      // (2, 256)
    const dim3 gsmall(NREL, 4);                 // tiny r-GEMM grid
    const size_t UPD_BYTES = sizeof(__half) * (size_t)NROW_H * E_;

    // ==== side stream: minimal scatter0 gate, then all prep + r-chain ========
    cudaEventRecord(eStart, 0);
    cudaStreamWaitEvent(s2, eStart, 0);
    cudaMemsetAsync(upd0, 0, UPD_BYTES, s2);
    cudaMemsetAsync(cnt,  0, sizeof(float) * NROW_H, s2);
    cudaEventRecord(eM0, s2);                               // scatter0 gate
    cudaMemsetAsync(upd1, 0, UPD_BYTES, s2);
    to_half<<<(VOCAB * E_ / 8 + 255) / 256, 256, 0, s2>>>(concept_table, ct16,
                                                          VOCAB * E_ / 8);
    cudaEventRecord(eCT, s2);                               // hgemm0 gate
    prep_weights<<<4 * MAT / 8 / 256, 256, 0, s2>>>(W_s, W_n, wf);
    cudaEventRecord(ePrepW, s2);                            // hgemm0 gate
    to_half<<<(NREL * E_ / 8 + 255) / 256, 256, 0, s2>>>(relation_table, rt16,
                                                         NREL * E_ / 8);
    to_half<<<(2 * MAT / 8 + 255) / 256, 256, 0, s2>>>(W_r, wr16, 2 * MAT / 8);
    small_gemm<true ><<<gsmall, 128, 0, s2>>>(rt16, wr16,       R0h, nullptr);
    cudaEventRecord(eR0, s2);                               // scatter1 gate
    small_gemm<false><<<gsmall, 128, 0, s2>>>(R0h,  wr16 + MAT, nullptr, R1f);
    write_rslice<<<NROW_R, 128, 0, s2>>>(R1f, relation_ids, out);
    cudaEventRecord(eSide, s2);                             // final gate

    // ==== main: hop-0 h-chain (scatter0 reads fp32 tables directly) ==========
    cudaStreamWaitEvent(0, eM0, 0);
    scatter_upd<true><<<NROW_R, 128>>>(head_idx, tail_idx, labels,
                                       concept_ids, relation_ids,
                                       concept_table, relation_table,
                                       nullptr, nullptr, upd0, cnt);
    cudaStreamWaitEvent(0, eCT, 0);
    cudaStreamWaitEvent(0, ePrepW, 0);
    gemm_fp16<2, true, true, true><<<gh, 256>>>(
        ct16, concept_ids, wf + 0 * (size_t)MAT,
        upd0, wf + 2 * (size_t)MAT, cnt, h16, E_, 0);

    // ==== main: hop-1 h-chain (needs R0 + cleared upd1 from side stream) =====
    cudaStreamWaitEvent(0, eR0, 0);
    scatter_upd<false><<<NROW_R, 128>>>(head_idx, tail_idx, labels,
                                        concept_ids, relation_ids,
                                        nullptr, nullptr, h16, R0h, upd1, cnt);
    gemm_fp16<2, true, true, true><<<gh, 256>>>(
        h16, nullptr, wf + 1 * (size_t)MAT,
        upd1, wf + 3 * (size_t)MAT, cnt, h2h, E_, 0);

    // ==== final: slices 0 and 2 (slice 1 written by side stream) =============
    cudaStreamWaitEvent(0, eSide, 0);
    final_gather02<<<NROW_R, 128>>>(h2h, head_idx, tail_idx, out);
}

// round 17
// speedup vs baseline: 1.3439x; 1.0132x over previous
#include <cuda_runtime.h>
#include <cuda_fp16.h>
#include <cstdint>
#include <cstring>

// Problem constants (fixed by the dataset)
#define B_    16
#define MC    2048
#define MT    4096
#define E_    512
#define VOCAB 32000
#define NREL  69

#define NROW_H (B_ * MC)   // 32768
#define NROW_R (B_ * MT)   // 65536
#define MAT    (E_ * E_)   // 262144

// ---------------- scratch (static device globals; no allocation allowed) ---
__device__ __half g_ct16[VOCAB * E_];            // fp16 concept table
__device__ __half g_rt16[NREL * E_];             // fp16 relation table
__device__ __half g_wr16[2 * MAT];               // fp16 plain Wr0, Wr1
__device__ __half g_R0h [NREL * E_];             // r embeddings after hop 0
__device__ float  g_R1f [NREL * E_];             // r embeddings after hop 1
__device__ __half g_h16[NROW_H * E_];            // h after hop 0 (fp16)
__device__ __half g_h2h[NROW_H * E_];            // h after hop 1 (fp16)
__device__ __half g_upd0[NROW_H * E_];           // hop-0 upd (fp16 atomics)
__device__ __half g_upd1[NROW_H * E_];           // hop-1 upd (fp16 atomics)
__device__ float  g_cnt [NROW_H];                // degree counts (both hops)
__device__ __half g_wf [4 * MAT];                // fp16 pre-swizzled weights
                                                 // [Ws0,Ws1,Wn0,Wn1]

// ---------------- bit-cast helpers --------------------------------------------
__device__ __forceinline__ uint32_t h2u(__half2 v) {
    uint32_t r;
    memcpy(&r, &v, 4);
    return r;
}
__device__ __forceinline__ __half2 u2h(uint32_t v) {
    __half2 r;
    memcpy(&r, &v, 4);
    return r;
}

// ---------------- mma / ldmatrix helpers -------------------------------------
__device__ __forceinline__ void ldsm4(uint32_t* r, uint32_t addr) {
    asm volatile("ldmatrix.sync.aligned.m8n8.x4.shared.b16 {%0,%1,%2,%3}, [%4];"
                 : "=r"(r[0]), "=r"(r[1]), "=r"(r[2]), "=r"(r[3]) : "r"(addr));
}

__device__ __forceinline__ void mma_fp16(float* c, const uint32_t* a,
                                         uint32_t b0, uint32_t b1) {
    asm volatile(
        "mma.sync.aligned.m16n8k16.row.col.f32.f16.f16.f32 "
        "{%0,%1,%2,%3}, {%4,%5,%6,%7}, {%8,%9}, {%0,%1,%2,%3};\n"
        : "+f"(c[0]), "+f"(c[1]), "+f"(c[2]), "+f"(c[3])
        : "r"(a[0]), "r"(a[1]), "r"(a[2]), "r"(a[3]), "r"(b0), "r"(b1));
}

// ---------------- fp32 -> fp16 conversion ------------------------------------
__global__ void to_half(const float* __restrict__ src, __half* __restrict__ dst,
                        int n8) {
    const int i = blockIdx.x * 256 + threadIdx.x;   // one 8-elem chunk each
    if (i >= n8) return;
    float4 a = ((const float4*)src)[2 * i];
    float4 b = ((const float4*)src)[2 * i + 1];
    uint4 o;
    o.x = h2u(__floats2half2_rn(a.x, a.y));
    o.y = h2u(__floats2half2_rn(a.z, a.w));
    o.z = h2u(__floats2half2_rn(b.x, b.y));
    o.w = h2u(__floats2half2_rn(b.z, b.w));
    ((uint4*)dst)[i] = o;
}

// ---------------- weight prep: fp32 row-major -> fp16 pre-swizzled tiles ----
__global__ void prep_weights(const float* __restrict__ Ws,
                             const float* __restrict__ Wn,
                             __half* __restrict__ dst) {
    const int idx = blockIdx.x * 256 + threadIdx.x;   // one 16B unit each
    const int mat  = idx >> 15;                       // 0..3
    const int rem  = idx & 32767;
    const int p    = rem >> 14;
    const int s    = (rem >> 10) & 15;
    const int nl   = (rem >> 2) & 255;
    const int u    = rem & 3;
    const float* src = (mat < 2) ? Ws + (size_t)mat * MAT
                                 : Wn + (size_t)(mat - 2) * MAT;
    const float* sp = src + (size_t)(p * 256 + nl) * E_ + s * 32 + u * 8;
    float4 v0 = ((const float4*)sp)[0];
    float4 v1 = ((const float4*)sp)[1];
    uint4 o;
    o.x = h2u(__floats2half2_rn(v0.x, v0.y));
    o.y = h2u(__floats2half2_rn(v0.z, v0.w));
    o.z = h2u(__floats2half2_rn(v1.x, v1.y));
    o.w = h2u(__floats2half2_rn(v1.z, v1.w));
    const int up = u ^ ((nl >> 1) & 3);
    *(uint4*)(dst + (size_t)mat * MAT + ((p * 16 + s) * 8192) + nl * 32 + up * 8) = o;
}

// ---------------- tiny r-GEMM: out[row][n] = sum_k A[row][k] * W[n][k] -------
// grid (NREL, 4): block (row, 128-col slice), 128 threads = 1 col each.
template<bool OUT16>
__global__ void __launch_bounds__(128)
small_gemm(const __half* __restrict__ A, const __half* __restrict__ W,
           __half* __restrict__ out16, float* __restrict__ out32) {
    __shared__ float arow[E_];
    const int row = blockIdx.x;
    const int n   = blockIdx.y * 128 + threadIdx.x;
    #pragma unroll
    for (int j = 0; j < 2; ++j) {
        const int idx = threadIdx.x * 2 + j;
        float2 f = __half22float2(((const __half2*)(A + (size_t)row * E_))[idx]);
        arow[2 * idx]     = f.x;
        arow[2 * idx + 1] = f.y;
    }
    __syncthreads();
    const __half2* w2 = (const __half2*)(W + (size_t)n * E_);
    float s = 0.0f;
    #pragma unroll 16
    for (int k = 0; k < E_ / 2; ++k) {
        float2 wf = __half22float2(w2[k]);
        s += arow[2 * k] * wf.x + arow[2 * k + 1] * wf.y;
    }
    if (OUT16) out16[(size_t)row * E_ + n] = __float2half_rn(s);
    else       out32[(size_t)row * E_ + n] = s;
}

// ---------------- scatter messages (+ degree counts on hop 0 only) ----------
__device__ __forceinline__ void red_h2(__half* p, float a, float b) {
    const uint32_t v = h2u(__floats2half2_rn(a, b));
    asm volatile("red.global.add.noftz.f16x2 [%0], %1;"
                 :: "l"(p), "r"(v) : "memory");
}

__device__ __forceinline__ float4 ld_half4(const __half* p, int o) {
    const __half2* q = (const __half2*)(p + o);
    float2 f0 = __half22float2(q[0]);
    float2 f1 = __half22float2(q[1]);
    return make_float4(f0.x, f0.y, f1.x, f1.y);
}

// Two triples per 256-thread block (half-block each).
// FIRST: h/r rows read straight from the fp32 tables (double indirection for h).
// Otherwise: h16 rows direct, r rows from fp16 R0h. cnt atomics on hop 0 only.
template<bool FIRST>
__global__ void __launch_bounds__(256)
scatter_upd(const int* __restrict__ head,
            const int* __restrict__ tail,
            const int* __restrict__ labels,
            const int* __restrict__ concept_ids,
            const int* __restrict__ relation_ids,
            const float* __restrict__ ctabf,
            const float* __restrict__ rtabf,
            const __half* __restrict__ h16,
            const __half* __restrict__ rtab16,
            __half* __restrict__ upd,
            float* __restrict__ cnt) {
    const int t = blockIdx.x * 2 + (threadIdx.x >> 7);
    if (labels[t] == -1) return;
    const int b  = t / MT;
    const size_t rowh = (size_t)b * MC + head[t];
    const size_t rowt = (size_t)b * MC + tail[t];

    const int i = threadIdx.x & 127;           // 0..127
    const int o = 4 * i;
    float4 hv, tv, rv;
    if (FIRST) {
        hv = ((const float4*)(ctabf + (size_t)concept_ids[rowh] * E_))[i];
        tv = ((const float4*)(ctabf + (size_t)concept_ids[rowt] * E_))[i];
        rv = ((const float4*)(rtabf + (size_t)relation_ids[t] * E_))[i];
    } else {
        hv = ld_half4(h16 + rowh * E_, o);
        tv = ld_half4(h16 + rowt * E_, o);
        rv = ld_half4(rtab16 + (size_t)relation_ids[t] * E_, o);
    }
    __half* ut = upd + rowt * E_;
    __half* uh = upd + rowh * E_;
    red_h2(ut + o,     hv.x - rv.x, hv.y - rv.y);
    red_h2(ut + o + 2, hv.z - rv.z, hv.w - rv.w);
    red_h2(uh + o,     tv.x - rv.x, tv.y - rv.y);
    red_h2(uh + o + 2, tv.z - rv.z, tv.w - rv.w);
    if (FIRST && i == 0) {
        atomicAdd(cnt + rowt, 1.0f);
        atomicAdd(cnt + rowh, 1.0f);
    }
}

// ==================== fp16 tensor-core GEMM NT (proven core) =================
// CTA 128x256, BK=32, double-buffered, 256 threads = 8 warps, 64x64 warp tiles.
// upd path stays fp16 end-to-end: __hmul2 by half2(1/clip(cnt,1)).
template<int NSRC, bool RELU, bool A0HALF, bool CHALF>
__global__ __launch_bounds__(256, 1)
void gemm_fp16(const void* __restrict__ A0v, const int* __restrict__ ids0,
               const __half* __restrict__ Wf0,
               const __half* __restrict__ A1, const __half* __restrict__ Wf1,
               const float* __restrict__ cnt,
               void* __restrict__ Cv, int ldc, int coff) {
    constexpr int KT = E_ / 32;                // 16 K-slices per source
    constexpr int TOTAL = NSRC * KT;

    __shared__ __align__(16) char sm[49152];   // As[2]:0,8K  Bs[2]:16K,32K
    const uint32_t sbase = (uint32_t)__cvta_generic_to_shared(sm);

    const int tid  = threadIdx.x;
    const int lane = tid & 31;
    const int wq   = tid >> 5;                 // warp 0..7
    const int wm   = (wq >> 2) * 64;
    const int wn   = (wq & 3) * 64;
    const int bm   = blockIdx.y * 128;
    const int bn   = blockIdx.x * 256;

    // ---- A staging: thread owns 4-elem chunk aj of rows ar+32*i, i=0..3 ----
    const int ar = tid >> 3;                   // 0..31
    const int aj = tid & 7;
    const int adst0 = ar * 64 + (((aj >> 1) ^ ((ar >> 1) & 3)) << 4) + ((aj & 1) << 3);
    const __half* Ah[4]; const float* Af[4]; const __half* Au[4];
    __half2 sch[4];
    #pragma unroll
    for (int i = 0; i < 4; ++i) {
        const int gr = bm + ar + 32 * i;
        const int gi = ids0 ? ids0[gr] : gr;
        if (A0HALF) Ah[i] = (const __half*)A0v + (size_t)gi * E_ + aj * 4;
        else        Af[i] = (const float*)A0v + (size_t)gi * E_ + aj * 4;
        if (NSRC == 2) {
            Au[i] = A1 + (size_t)gr * E_ + aj * 4;
            sch[i] = __float2half2_rn(1.0f / fmaxf(cnt[gr], 1.0f));
        }
    }

    // ---- B staging: 4 x uint4 of the 16KB pre-swizzled slice ----
    const __half* Bt0 = Wf0 + (size_t)blockIdx.x * 16 * 8192 + tid * 8;
    const __half* Bt1 = (NSRC == 2) ? (Wf1 + (size_t)blockIdx.x * 16 * 8192 + tid * 8) : nullptr;

    // ---- ldmatrix fragment offsets ----
    const int mloc  = (lane & 7) + ((lane >> 3) & 1) * 8;
    const int khalf = lane >> 4;
    int aoff[4][2], boff[4][2];
    #pragma unroll
    for (int f = 0; f < 4; ++f) {
        const int row = wm + f * 16 + mloc;
        const int sw  = (row >> 1) & 3;
        #pragma unroll
        for (int kk = 0; kk < 2; ++kk)
            aoff[f][kk] = row * 64 + ((((kk << 1) | khalf) ^ sw) << 4);
    }
    #pragma unroll
    for (int q = 0; q < 4; ++q) {
        const int row = wn + q * 16 + mloc;
        const int sw  = (row >> 1) & 3;
        #pragma unroll
        for (int kk = 0; kk < 2; ++kk)
            boff[q][kk] = row * 64 + ((((kk << 1) | khalf) ^ sw) << 4);
    }

    float4 la[4];
    uint2  lau[4];
    bool   conv = false;
    uint4  lb[4];

    float acc[4][8][4];
    #pragma unroll
    for (int f = 0; f < 4; ++f)
        #pragma unroll
        for (int g = 0; g < 8; ++g)
            #pragma unroll
            for (int e = 0; e < 4; ++e) acc[f][g][e] = 0.0f;

    auto ldg = [&](int t) {
        const bool sec = (NSRC == 2) && (t >= KT);
        const int s = t & (KT - 1);
        if (sec) {
            #pragma unroll
            for (int i = 0; i < 4; ++i) {
                uint2 v = *(const uint2*)(Au[i] + s * 32);
                lau[i].x = h2u(__hmul2(u2h(v.x), sch[i]));
                lau[i].y = h2u(__hmul2(u2h(v.y), sch[i]));
            }
            conv = false;
        } else if (A0HALF) {
            #pragma unroll
            for (int i = 0; i < 4; ++i) lau[i] = *(const uint2*)(Ah[i] + s * 32);
            conv = false;
        } else {
            #pragma unroll
            for (int i = 0; i < 4; ++i) la[i] = *(const float4*)(Af[i] + s * 32);
            conv = true;
        }
        const __half* bp = (sec ? Bt1 : Bt0) + (size_t)s * 8192;
        #pragma unroll
        for (int q = 0; q < 4; ++q) lb[q] = *(const uint4*)(bp + q * 2048);
    };

    auto sts = [&](int buf) {
        char* ab = sm + buf * 8192;
        #pragma unroll
        for (int i = 0; i < 4; ++i) {
            uint2 v;
            if (conv) {
                v.x = h2u(__floats2half2_rn(la[i].x, la[i].y));
                v.y = h2u(__floats2half2_rn(la[i].z, la[i].w));
            } else {
                v = lau[i];
            }
            *(uint2*)(ab + adst0 + i * 2048) = v;   // +32 rows = +2048 B
        }
        char* bb = sm + 16384 + buf * 16384;
        #pragma unroll
        for (int q = 0; q < 4; ++q)
            *(uint4*)(bb + tid * 16 + q * 4096) = lb[q];
    };

    auto compute = [&](int buf) {
        const uint32_t ab = sbase + buf * 8192;
        const uint32_t bb = sbase + 16384 + buf * 16384;
        #pragma unroll
        for (int kk = 0; kk < 2; ++kk) {
            uint32_t a[4][4];
            #pragma unroll
            for (int f = 0; f < 4; ++f) ldsm4(a[f], ab + aoff[f][kk]);
            #pragma unroll
            for (int q = 0; q < 4; ++q) {
                uint32_t b[4];
                ldsm4(b, bb + boff[q][kk]);
                #pragma unroll
                for (int f = 0; f < 4; ++f) {
                    mma_fp16(acc[f][q * 2 + 0], a[f], b[0], b[2]);
                    mma_fp16(acc[f][q * 2 + 1], a[f], b[1], b[3]);
                }
            }
        }
    };

    // ---- pipeline ----
    ldg(0);
    sts(0);
    __syncthreads();
    for (int t = 0; t < TOTAL; ++t) {
        const int buf = t & 1;
        if (t + 1 < TOTAL) ldg(t + 1);
        compute(buf);
        if (t + 1 < TOTAL) {
            sts(buf ^ 1);
            __syncthreads();
        }
    }

    // ---- epilogue: warp tile 64x64 ----
    #pragma unroll
    for (int f = 0; f < 4; ++f) {
        #pragma unroll
        for (int g = 0; g < 8; ++g) {
            const int row0 = bm + wm + f * 16 + (lane >> 2);
            const int col  = wn + g * 8 + (lane & 3) * 2;
            float2 v0 = make_float2(acc[f][g][0], acc[f][g][1]);
            float2 v1 = make_float2(acc[f][g][2], acc[f][g][3]);
            if (RELU) {
                v0.x = fmaxf(v0.x, 0.f); v0.y = fmaxf(v0.y, 0.f);
                v1.x = fmaxf(v1.x, 0.f); v1.y = fmaxf(v1.y, 0.f);
            }
            if (CHALF) {
                __half* Ch = (__half*)Cv;
                *(uint32_t*)&Ch[(size_t)row0 * E_ + bn + col] =
                    h2u(__floats2half2_rn(v0.x, v0.y));
                *(uint32_t*)&Ch[(size_t)(row0 + 8) * E_ + bn + col] =
                    h2u(__floats2half2_rn(v1.x, v1.y));
            } else {
                float* Cf = (float*)Cv;
                *(float2*)&Cf[(size_t)row0 * ldc + coff + bn + col]       = v0;
                *(float2*)&Cf[(size_t)(row0 + 8) * ldc + coff + bn + col] = v1;
            }
        }
    }
}

// ---------------- out slice 1: out[t][512:1024] = R1[rel_ids[t]] -------------
// Two triples per 256-thread block.
__global__ void __launch_bounds__(256)
write_rslice(const float* __restrict__ R1,
             const int* __restrict__ relation_ids,
             float* __restrict__ out) {
    const int t = blockIdx.x * 2 + (threadIdx.x >> 7);
    const int i = threadIdx.x & 127;
    const float4* rr = (const float4*)(R1 + (size_t)relation_ids[t] * E_);
    float4* o = (float4*)(out + (size_t)t * 3 * E_);
    o[128 + i] = rr[i];
}

// ---------------- final: out slices 0 and 2 (two triples per block) ----------
__global__ void __launch_bounds__(256)
final_gather02(const __half* __restrict__ h2,
               const int* __restrict__ head,
               const int* __restrict__ tail,
               float* __restrict__ out) {
    const int t = blockIdx.x * 2 + (threadIdx.x >> 7);
    const int b = t / MT;
    const int i = threadIdx.x & 127;
    const __half* hh = h2 + ((size_t)b * MC + head[t]) * E_;
    const __half* ht = h2 + ((size_t)b * MC + tail[t]) * E_;
    float4* o = (float4*)(out + (size_t)t * 3 * E_);
    const int off = 4 * i;
    o[i]       = ld_half4(hh, off);
    o[256 + i] = ld_half4(ht, off);
}

// ---------------- host launch ------------------------------------------------
extern "C" void kernel_launch(void* const* d_in, const int* in_sizes, int n_in,
                              void* d_out, int out_size) {
    const float* concept_table  = (const float*)d_in[0];
    const float* relation_table = (const float*)d_in[1];
    const float* W_s            = (const float*)d_in[2];
    const float* W_n            = (const float*)d_in[3];
    const float* W_r            = (const float*)d_in[4];
    const int*   concept_ids    = (const int*)d_in[5];
    const int*   relation_ids   = (const int*)d_in[6];
    const int*   head_idx       = (const int*)d_in[7];
    const int*   tail_idx       = (const int*)d_in[8];
    const int*   labels         = (const int*)d_in[9];
    float*       out            = (float*)d_out;

    __half *ct16, *rt16, *wr16, *R0h, *h16, *h2h, *upd0, *upd1, *wf;
    float *R1f, *cnt;
    cudaGetSymbolAddress((void**)&ct16, g_ct16);
    cudaGetSymbolAddress((void**)&rt16, g_rt16);
    cudaGetSymbolAddress((void**)&wr16, g_wr16);
    cudaGetSymbolAddress((void**)&R0h,  g_R0h);
    cudaGetSymbolAddress((void**)&R1f,  g_R1f);
    cudaGetSymbolAddress((void**)&h16,  g_h16);
    cudaGetSymbolAddress((void**)&h2h,  g_h2h);
    cudaGetSymbolAddress((void**)&upd0, g_upd0);
    cudaGetSymbolAddress((void**)&upd1, g_upd1);
    cudaGetSymbolAddress((void**)&cnt,  g_cnt);
    cudaGetSymbolAddress((void**)&wf,   g_wf);

    cudaStream_t s2;
    cudaStreamCreateWithFlags(&s2, cudaStreamNonBlocking);
    cudaEvent_t eStart, eM0, eCT, ePrepW, eR0, eSide;
    cudaEventCreateWithFlags(&eStart, cudaEventDisableTiming);
    cudaEventCreateWithFlags(&eM0,    cudaEventDisableTiming);
    cudaEventCreateWithFlags(&eCT,    cudaEventDisableTiming);
    cudaEventCreateWithFlags(&ePrepW, cudaEventDisableTiming);
    cudaEventCreateWithFlags(&eR0,    cudaEventDisableTiming);
    cudaEventCreateWithFlags(&eSide,  cudaEventDisableTiming);

    const dim3 gh(E_ / 256, NROW_H / 128);      // (2, 256)
    const dim3 gsmall(NREL, 4);                 // tiny r-GEMM grid
    const size_t UPD_BYTES = sizeof(__half) * (size_t)NROW_H * E_;

    // ==== side stream: minimal scatter0 gate, then all prep + r-chain ========
    cudaEventRecord(eStart, 0);
    cudaStreamWaitEvent(s2, eStart, 0);
    cudaMemsetAsync(upd0, 0, UPD_BYTES, s2);
    cudaMemsetAsync(cnt,  0, sizeof(float) * NROW_H, s2);
    cudaEventRecord(eM0, s2);                               // scatter0 gate
    cudaMemsetAsync(upd1, 0, UPD_BYTES, s2);
    to_half<<<(VOCAB * E_ / 8 + 255) / 256, 256, 0, s2>>>(concept_table, ct16,
                                                          VOCAB * E_ / 8);
    cudaEventRecord(eCT, s2);                               // hgemm0 gate
    prep_weights<<<4 * MAT / 8 / 256, 256, 0, s2>>>(W_s, W_n, wf);
    cudaEventRecord(ePrepW, s2);                            // hgemm0 gate
    to_half<<<(NREL * E_ / 8 + 255) / 256, 256, 0, s2>>>(relation_table, rt16,
                                                         NREL * E_ / 8);
    to_half<<<(2 * MAT / 8 + 255) / 256, 256, 0, s2>>>(W_r, wr16, 2 * MAT / 8);
    small_gemm<true ><<<gsmall, 128, 0, s2>>>(rt16, wr16,       R0h, nullptr);
    cudaEventRecord(eR0, s2);                               // scatter1 gate
    small_gemm<false><<<gsmall, 128, 0, s2>>>(R0h,  wr16 + MAT, nullptr, R1f);
    write_rslice<<<NROW_R / 2, 256, 0, s2>>>(R1f, relation_ids, out);
    cudaEventRecord(eSide, s2);                             // final gate

    // ==== main: hop-0 h-chain (scatter0 reads fp32 tables directly) ==========
    cudaStreamWaitEvent(0, eM0, 0);
    scatter_upd<true><<<NROW_R / 2, 256>>>(head_idx, tail_idx, labels,
                                           concept_ids, relation_ids,
                                           concept_table, relation_table,
                                           nullptr, nullptr, upd0, cnt);
    cudaStreamWaitEvent(0, eCT, 0);
    cudaStreamWaitEvent(0, ePrepW, 0);
    gemm_fp16<2, true, true, true><<<gh, 256>>>(
        ct16, concept_ids, wf + 0 * (size_t)MAT,
        upd0, wf + 2 * (size_t)MAT, cnt, h16, E_, 0);

    // ==== main: hop-1 h-chain (needs R0 + cleared upd1 from side stream) =====
    cudaStreamWaitEvent(0, eR0, 0);
    scatter_upd<false><<<NROW_R / 2, 256>>>(head_idx, tail_idx, labels,
                                            concept_ids, relation_ids,
                                            nullptr, nullptr, h16, R0h,
                                            upd1, cnt);
    gemm_fp16<2, true, true, true><<<gh, 256>>>(
        h16, nullptr, wf + 1 * (size_t)MAT,
        upd1, wf + 3 * (size_t)MAT, cnt, h2h, E_, 0);

    // ==== final: slices 0 and 2 (slice 1 written by side stream) =============
    cudaStreamWaitEvent(0, eSide, 0);
    final_gather02<<<NROW_R / 2, 256>>>(h2h, head_idx, tail_idx, out);
}